// round 5
// baseline (speedup 1.0000x reference)
#include <cuda_runtime.h>
#include <cstdint>

// Problem dims
#define NB    4096
#define IN_D  1024
#define NH0   4000
#define NH1   4000
#define NR    2000
#define NOUT  10
#define KP0   4096      // padded K, out-half  ([spk_out|pad][spk_in|pad])
#define KP1   8192      // padded K, in-half   (+ [spk1n|pad])
#define NPAD  2048

#define BASE_THRE 0.1f
#define R_M       3.0f
#define BETA      1.8f

// digit fold scales: w = (hi*2^16 + mid*2^8 + lo) * 2^-27
#define SC_HI  4.8828125e-4f            // 2^-11
#define SC_MID 1.9073486328125e-6f      // 2^-19
#define SC_LO  7.450580596923828e-9f    // 2^-27

// ---------------------------------------------------------------------------
// Static device scratch (zero-initialized; pad regions stay zero forever)
// ---------------------------------------------------------------------------
__device__ __align__(256) signed char g_W8o[3][(size_t)NPAD * KP0];  // 25MB
__device__ __align__(256) signed char g_W8i[3][(size_t)NPAD * KP1];  // 50MB
__device__ __align__(256) signed char g_A8[(size_t)NB * KP1];        // 32MB
__device__ float g_stm2[NH1];
__device__ float g_sta2[NH1];
__device__ float g_bias2[NH1];

__device__ __forceinline__ float sigm(float x) { return 1.0f / (1.0f + expf(-x)); }

__device__ __forceinline__ uint32_t smem_u32(const void* p) {
    uint32_t a;
    asm("{ .reg .u64 t; cvta.to.shared.u64 t, %1; cvt.u32.u64 %0, t; }" : "=r"(a) : "l"(p));
    return a;
}
__device__ __forceinline__ void cp16(uint32_t dst, const void* src) {
    asm volatile("cp.async.cg.shared.global [%0], [%1], 16;" :: "r"(dst), "l"(src) : "memory");
}
#define CP_COMMIT() asm volatile("cp.async.commit_group;" ::: "memory")
#define CP_WAIT2()  asm volatile("cp.async.wait_group 2;" ::: "memory")

__device__ __forceinline__ void ldm_x4(uint32_t& r0, uint32_t& r1, uint32_t& r2, uint32_t& r3,
                                       uint32_t addr) {
    asm volatile("ldmatrix.sync.aligned.m8n8.x4.shared.b16 {%0,%1,%2,%3}, [%4];"
                 : "=r"(r0), "=r"(r1), "=r"(r2), "=r"(r3) : "r"(addr));
}
// int8 MMA: D(s32) += A(s8,m16k32) * B(s8,n8k32)
__device__ __forceinline__ void imma16832(int* c, const uint32_t* a, uint32_t b0, uint32_t b1) {
    asm volatile(
        "mma.sync.aligned.m16n8k32.row.col.s32.s8.s8.s32 "
        "{%0,%1,%2,%3}, {%4,%5,%6,%7}, {%8,%9}, {%0,%1,%2,%3};"
        : "+r"(c[0]), "+r"(c[1]), "+r"(c[2]), "+r"(c[3])
        : "r"(a[0]), "r"(a[1]), "r"(a[2]), "r"(a[3]), "r"(b0), "r"(b1));
}

// signed 3-digit decomposition of round(w * 2^27); |w| <= 0.039 -> |hi| <= 81
__device__ __forceinline__ void digits3(float w, signed char& hi, signed char& mid,
                                        signed char& lo) {
    int w27 = (int)lrintf(w * 134217728.0f);
    int l   = (w27 << 24) >> 24;
    int t   = (w27 - l) >> 8;
    int m   = (t << 24) >> 24;
    int h   = (t - m) >> 8;
    hi = (signed char)h; mid = (signed char)m; lo = (signed char)l;
}

// ---------------------------------------------------------------------------
// Weight conversion: fp32 -> 3 s8 digit planes, packed K layout; col params
// ---------------------------------------------------------------------------
__global__ void convW8_kernel(
    const float* __restrict__ rec4out, const float* __restrict__ in2out,
    const float* __restrict__ out2in,  const float* __restrict__ rec4in,
    const float* __restrict__ x2in,
    const float* __restrict__ tau_m2,  const float* __restrict__ tau_adp2,
    const float* __restrict__ rec4out_b, const float* __restrict__ in2out_b,
    const float* __restrict__ out2in_b,  const float* __restrict__ rec4in_b,
    const float* __restrict__ x2in_b)
{
    const long S1 = (long)NR * NR;
    const long S2 = (long)NR * NH0;
    long i = (long)blockIdx.x * blockDim.x + threadIdx.x;
    if (i < 4 * S1) {
        int sel = (int)(i / S1);
        long r  = i % S1;
        int n = (int)(r / NR), k = (int)(r % NR);
        float w; size_t dst; int which;
        if (sel == 0)      { w = rec4out[r]; dst = (size_t)n * KP0 + k;        which = 0; }
        else if (sel == 1) { w = in2out[r];  dst = (size_t)n * KP0 + 2048 + k; which = 0; }
        else if (sel == 2) { w = out2in[r];  dst = (size_t)n * KP1 + k;        which = 1; }
        else               { w = rec4in[r];  dst = (size_t)n * KP1 + 2048 + k; which = 1; }
        signed char h, m, l; digits3(w, h, m, l);
        if (which == 0) { g_W8o[0][dst] = h; g_W8o[1][dst] = m; g_W8o[2][dst] = l; }
        else            { g_W8i[0][dst] = h; g_W8i[1][dst] = m; g_W8i[2][dst] = l; }
    } else if (i < 4 * S1 + S2) {
        long r = i - 4 * S1;
        int n = (int)(r / NH0), k = (int)(r % NH0);
        signed char h, m, l; digits3(x2in[r], h, m, l);
        size_t dst = (size_t)n * KP1 + 4096 + k;
        g_W8i[0][dst] = h; g_W8i[1][dst] = m; g_W8i[2][dst] = l;
    } else if (i < 4 * S1 + S2 + NH1) {
        int g = (int)(i - 4 * S1 - S2);
        g_stm2[g] = sigm(tau_m2[g]);
        g_sta2[g] = sigm(tau_adp2[g]);
        g_bias2[g] = (g < NR) ? (rec4out_b[g] + in2out_b[g])
                              : (x2in_b[g - NR] + rec4in_b[g - NR] + out2in_b[g - NR]);
    }
}

// Pack spikes (exact {0,1}) into s8 A: [spk_out|0][spk_in|0][spk1n|0]
__global__ void convA8_kernel(const float* __restrict__ spk2, const float* __restrict__ spk1n)
{
    const long T1 = (long)NB * NH1;
    long i = (long)blockIdx.x * blockDim.x + threadIdx.x;
    if (i < T1) {
        int b = (int)(i / NH1), k = (int)(i % NH1);
        g_A8[(size_t)b * KP1 + (k < NR ? k : k + 48)] = (signed char)(spk2[i] > 0.5f);
    } else if (i < 2 * T1) {
        long r = i - T1;
        int b = (int)(r / NH0), k = (int)(r % NH0);
        g_A8[(size_t)b * KP1 + 4096 + k] = (signed char)(spk1n[r] > 0.5f);
    }
}

// ---------------------------------------------------------------------------
// GEMM2 via IMMA s8 (3 digit phases, exact s32 accumulation, float fold per
// phase). CTA tile 128x128, BK=64 bytes, 4-stage cp.async, fused mem_update2.
//   grid: (32 m-tiles, 16 n-tiles, 2 modes)  block: 256 (8 warps, 2x4)
// ---------------------------------------------------------------------------
#define ROWB   80
#define TILEI  (128 * ROWB)          // 10240 (A or W tile: 64B data + 16B pad per row)
#define STGI   (2 * TILEI)           // 20480 per stage
#define SMEM_I8 (4 * STGI)           // 81920

__global__ void __launch_bounds__(256, 1) gemm2_i8_kernel(
    const float* __restrict__ spk2, const float* __restrict__ mem2,
    const float* __restrict__ b2,
    float* __restrict__ out_mem2, float* __restrict__ out_spk2, float* __restrict__ out_b2)
{
    extern __shared__ char smem[];
    const uint32_t sb = smem_u32(smem);
    const int tid  = threadIdx.x;
    const int wid  = tid >> 5;
    const int lane = tid & 31;
    const int mode = blockIdx.z;
    const int m0   = blockIdx.x * 128;
    const int n0   = blockIdx.y * 128;

    const int Kpad = mode ? KP1 : KP0;
    const int C    = Kpad / 64;          // chunks per phase (64 or 128)
    const int Q    = 3 * C;              // total iterations (3 digit phases)

    const signed char* A0 = g_A8 + (size_t)m0 * KP1;
    const signed char* W0 = (mode ? &g_W8i[0][0] : &g_W8o[0][0]) + (size_t)n0 * Kpad;
    const signed char* W1 = (mode ? &g_W8i[1][0] : &g_W8o[1][0]) + (size_t)n0 * Kpad;
    const signed char* W2 = (mode ? &g_W8i[2][0] : &g_W8o[2][0]) + (size_t)n0 * Kpad;

    const int row0 = tid >> 2;           // 0..63
    const int ch0  = tid & 3;            // 16B chunk within 64B row

    auto issue = [&](int q) {
        const signed char* w;
        int c;
        if (q >= 2 * C)      { w = W2; c = q - 2 * C; }
        else if (q >= C)     { w = W1; c = q - C; }
        else                 { w = W0; c = q; }
        const uint32_t dst = sb + (q & 3) * STGI;
        const size_t koff = (size_t)c * 64 + ch0 * 16;
        #pragma unroll
        for (int j = 0; j < 2; j++) {
            const int row = row0 + j * 64;
            const uint32_t dofs = row * ROWB + ch0 * 16;
            cp16(dst + dofs, A0 + (size_t)row * KP1 + koff);
            cp16(dst + TILEI + dofs, w + (size_t)row * Kpad + koff);
        }
        CP_COMMIT();
    };

    const int wm = wid >> 2;     // 0..1
    const int wn = wid & 3;      // 0..3
    const int lrow = lane & 15;
    const int lcol = (lane >> 4) * 16;

    int   accI[4][4][4];
    float F[4][4][4];
    #pragma unroll
    for (int mi = 0; mi < 4; mi++)
        #pragma unroll
        for (int ni = 0; ni < 4; ni++)
            #pragma unroll
            for (int r = 0; r < 4; r++) { accI[mi][ni][r] = 0; F[mi][ni][r] = 0.f; }

    issue(0); issue(1); issue(2);

    int cc = 0, p = 0;
    for (int q = 0; q < Q; q++) {
        CP_WAIT2();
        __syncthreads();
        if (q + 3 < Q) issue(q + 3);
        else CP_COMMIT();                 // keep group accounting consistent

        const uint32_t stb = sb + (q & 3) * STGI;
        #pragma unroll
        for (int ks = 0; ks < 2; ks++) {
            uint32_t a[4][4];
            #pragma unroll
            for (int mi = 0; mi < 4; mi++) {
                const uint32_t ad = stb + (wm * 64 + mi * 16 + lrow) * ROWB + ks * 32 + lcol;
                ldm_x4(a[mi][0], a[mi][1], a[mi][2], a[mi][3], ad);
            }
            uint32_t b[4][2];
            #pragma unroll
            for (int nj = 0; nj < 2; nj++) {
                uint32_t r0, r1, r2, r3;
                const uint32_t bd = stb + TILEI
                                  + (wn * 32 + nj * 16 + lrow) * ROWB + ks * 32 + lcol;
                ldm_x4(r0, r1, r2, r3, bd);
                b[nj * 2 + 0][0] = r0; b[nj * 2 + 0][1] = r2;
                b[nj * 2 + 1][0] = r1; b[nj * 2 + 1][1] = r3;
            }
            #pragma unroll
            for (int mi = 0; mi < 4; mi++)
                #pragma unroll
                for (int ni = 0; ni < 4; ni++)
                    imma16832(accI[mi][ni], a[mi], b[ni][0], b[ni][1]);
        }

        if (++cc == C) {                  // end of digit phase: exact fold
            const float sc = (p == 0) ? SC_HI : (p == 1 ? SC_MID : SC_LO);
            #pragma unroll
            for (int mi = 0; mi < 4; mi++)
                #pragma unroll
                for (int ni = 0; ni < 4; ni++)
                    #pragma unroll
                    for (int r = 0; r < 4; r++) {
                        F[mi][ni][r] += sc * (float)accI[mi][ni][r];
                        accI[mi][ni][r] = 0;
                    }
            p++; cc = 0;
        }
    }

    // Epilogue: fused mem_update2 from folded accumulators
    const int erow = lane >> 2;
    const int ecol = (lane & 3) * 2;
    #pragma unroll
    for (int mi = 0; mi < 4; mi++) {
        #pragma unroll
        for (int r2i = 0; r2i < 2; r2i++) {
            const int m = m0 + wm * 64 + mi * 16 + erow + r2i * 8;
            const size_t rowo = (size_t)m * NH1;
            #pragma unroll
            for (int ni = 0; ni < 4; ni++) {
                #pragma unroll
                for (int cc2 = 0; cc2 < 2; cc2++) {
                    const int nl = n0 + wn * 32 + ni * 8 + ecol + cc2;
                    if (nl >= NR) continue;
                    const int g = mode * NR + nl;
                    const size_t idx = rowo + g;
                    const float v = F[mi][ni][r2i * 2 + cc2] + g_bias2[g];
                    const float tm = g_stm2[g], ta = g_sta2[g];
                    const float sp = spk2[idx];
                    const float bb = ta * b2[idx] + (1.f - ta) * sp;
                    const float thre = BASE_THRE + BETA * bb;
                    const float mem = mem2[idx] * tm + (1.f - tm) * R_M * v - thre * sp;
                    out_mem2[idx] = mem;
                    out_spk2[idx] = (mem - thre) > 0.f ? 1.f : 0.f;
                    out_b2[idx]   = bb;
                }
            }
        }
    }
}

// ---------------------------------------------------------------------------
// GEMM1 (fp32 FFMA, at roofline) — unchanged
// ---------------------------------------------------------------------------
__device__ __forceinline__ void gemm_seg(
    const float* __restrict__ A, int lda, int aoff,
    const float* __restrict__ Bm, int ldb, int K, int nmaxB,
    int m0, int n0, float* As, float* Bs, float acc[8][8])
{
    const int tid = threadIdx.x;
    const int ar = tid >> 2, ac = (tid & 3) << 2;
    const int ty = tid >> 4, tx = tid & 15;
    for (int k0 = 0; k0 < K; k0 += 16) {
        #pragma unroll
        for (int r = 0; r < 128; r += 64) {
            const float4 v = *(const float4*)(A + (size_t)(m0 + ar + r) * lda + (aoff + k0 + ac));
            As[(ac + 0) * 128 + ar + r] = v.x; As[(ac + 1) * 128 + ar + r] = v.y;
            As[(ac + 2) * 128 + ar + r] = v.z; As[(ac + 3) * 128 + ar + r] = v.w;
        }
        #pragma unroll
        for (int r = 0; r < 128; r += 64) {
            const int n = n0 + ar + r;
            float4 v = make_float4(0.f, 0.f, 0.f, 0.f);
            if (n < nmaxB) v = *(const float4*)(Bm + (size_t)n * ldb + (k0 + ac));
            Bs[(ac + 0) * 128 + ar + r] = v.x; Bs[(ac + 1) * 128 + ar + r] = v.y;
            Bs[(ac + 2) * 128 + ar + r] = v.z; Bs[(ac + 3) * 128 + ar + r] = v.w;
        }
        __syncthreads();
        #pragma unroll
        for (int kk = 0; kk < 16; kk++) {
            float a[8], b[8];
            #pragma unroll
            for (int i = 0; i < 8; i++) a[i] = As[kk * 128 + ty * 8 + i];
            #pragma unroll
            for (int j = 0; j < 8; j++) b[j] = Bs[kk * 128 + tx * 8 + j];
            #pragma unroll
            for (int i = 0; i < 8; i++)
                #pragma unroll
                for (int j = 0; j < 8; j++) acc[i][j] = fmaf(a[i], b[j], acc[i][j]);
        }
        __syncthreads();
    }
}

__global__ void __launch_bounds__(256, 2) gemm1_kernel(
    const float* __restrict__ x_t, const float* __restrict__ fc_w, const float* __restrict__ fc_b,
    const float* __restrict__ mem1, const float* __restrict__ spk1, const float* __restrict__ b1,
    const float* __restrict__ tau_m1, const float* __restrict__ tau_adp1,
    float* __restrict__ out_mem1, float* __restrict__ out_spk1, float* __restrict__ out_b1)
{
    __shared__ float As[16 * 128];
    __shared__ float Bs[16 * 128];
    const int n0 = blockIdx.x * 128, m0 = blockIdx.y * 128;
    float acc[8][8];
    #pragma unroll
    for (int i = 0; i < 8; i++)
        #pragma unroll
        for (int j = 0; j < 8; j++) acc[i][j] = 0.f;
    gemm_seg(x_t, IN_D, 0, fc_w, IN_D, IN_D, NH0, m0, n0, As, Bs, acc);
    const int ty = threadIdx.x >> 4, tx = threadIdx.x & 15;
    float tmv[8], tav[8], fbv[8];
    #pragma unroll
    for (int j = 0; j < 8; j++) {
        const int n = n0 + tx * 8 + j; const bool v = (n < NH0);
        tmv[j] = sigm(v ? tau_m1[n] : 0.f);
        tav[j] = sigm(v ? tau_adp1[n] : 0.f);
        fbv[j] = v ? fc_b[n] : 0.f;
    }
    #pragma unroll
    for (int i = 0; i < 8; i++) {
        const int m = m0 + ty * 8 + i;
        const size_t rowo = (size_t)m * NH0;
        #pragma unroll
        for (int j = 0; j < 8; j++) {
            const int n = n0 + tx * 8 + j;
            if (n >= NH0) continue;
            const size_t idx = rowo + n;
            const float sp = spk1[idx];
            const float bb = tav[j] * b1[idx] + (1.f - tav[j]) * sp;
            const float thre = BASE_THRE + BETA * bb;
            const float mem = mem1[idx] * tmv[j] + (1.f - tmv[j]) * R_M * (acc[i][j] + fbv[j])
                            - thre * sp;
            out_mem1[idx] = mem;
            out_spk1[idx] = (mem - thre) > 0.f ? 1.f : 0.f;
            out_b1[idx]   = bb;
        }
    }
}

// ---------------------------------------------------------------------------
// Head: pooling + mem_out update + log_softmax
// ---------------------------------------------------------------------------
__global__ void head_kernel(
    const float* __restrict__ spk2n, const float* __restrict__ mem_out,
    const float* __restrict__ out_tau_m,
    float* __restrict__ log_sm, float* __restrict__ mem_out_n)
{
    __shared__ float xo[NOUT];
    const int row = blockIdx.x;
    const int w = threadIdx.x >> 5, lane = threadIdx.x & 31;
    float s = 0.f;
    const float* p = spk2n + (size_t)row * NH1 + w * 200;
    for (int i = lane; i < 200; i += 32) s += p[i];
    #pragma unroll
    for (int o = 16; o > 0; o >>= 1) s += __shfl_down_sync(0xffffffffu, s, o);
    if (lane == 0) xo[w] = s;
    __syncthreads();
    if (threadIdx.x == 0) {
        float v[NOUT];
        float mx = -1e30f;
        #pragma unroll
        for (int o = 0; o < NOUT; o++) {
            const float m = mem_out[(size_t)row * NOUT + o];
            const float mo = m + (xo[o] - m) * sigm(out_tau_m[o]);
            v[o] = mo; mem_out_n[(size_t)row * NOUT + o] = mo;
            mx = fmaxf(mx, mo);
        }
        float se = 0.f;
        #pragma unroll
        for (int o = 0; o < NOUT; o++) se += expf(v[o] - mx);
        const float lse = mx + logf(se);
        #pragma unroll
        for (int o = 0; o < NOUT; o++) log_sm[(size_t)row * NOUT + o] = v[o] - lse;
    }
}

// ---------------------------------------------------------------------------
// Launch
// ---------------------------------------------------------------------------
extern "C" void kernel_launch(void* const* d_in, const int* in_sizes, int n_in,
                              void* d_out, int out_size)
{
    const float* x_t       = (const float*)d_in[0];
    const float* mem1      = (const float*)d_in[1];
    const float* spk1      = (const float*)d_in[2];
    const float* b1        = (const float*)d_in[3];
    const float* mem2      = (const float*)d_in[4];
    const float* spk2      = (const float*)d_in[5];
    const float* b2        = (const float*)d_in[6];
    const float* mem_out   = (const float*)d_in[7];
    const float* fc_w      = (const float*)d_in[8];
    const float* fc_b      = (const float*)d_in[9];
    const float* tau_adp1  = (const float*)d_in[10];
    const float* tau_m1    = (const float*)d_in[11];
    const float* x2in_w    = (const float*)d_in[12];
    const float* x2in_b    = (const float*)d_in[13];
    const float* rec4in_w  = (const float*)d_in[14];
    const float* rec4in_b  = (const float*)d_in[15];
    const float* in2out_w  = (const float*)d_in[16];
    const float* in2out_b  = (const float*)d_in[17];
    const float* rec4out_w = (const float*)d_in[18];
    const float* rec4out_b = (const float*)d_in[19];
    const float* out2in_w  = (const float*)d_in[20];
    const float* out2in_b  = (const float*)d_in[21];
    const float* tau_adp2  = (const float*)d_in[22];
    const float* tau_m2    = (const float*)d_in[23];
    const float* out_tau_m = (const float*)d_in[24];

    float* out = (float*)d_out;
    const size_t BH = (size_t)NB * NH0;
    float* log_sm    = out;
    float* mem1n     = out + (size_t)NB * NOUT;
    float* spk1n     = mem1n + BH;
    float* b1n       = spk1n + BH;
    float* mem2n     = b1n + BH;
    float* spk2n     = mem2n + BH;
    float* b2n       = spk2n + BH;
    float* mem_out_n = b2n + BH;

    cudaFuncSetAttribute(gemm2_i8_kernel, cudaFuncAttributeMaxDynamicSharedMemorySize,
                         SMEM_I8);

    // weight digitization can start immediately (independent of gemm1)
    {
        const long T = 4L * NR * NR + (long)NR * NH0 + NH1;
        convW8_kernel<<<(int)((T + 255) / 256), 256>>>(
            rec4out_w, in2out_w, out2in_w, rec4in_w, x2in_w,
            tau_m2, tau_adp2, rec4out_b, in2out_b, out2in_b, rec4in_b, x2in_b);
    }

    gemm1_kernel<<<dim3(32, 32), 256>>>(
        x_t, fc_w, fc_b, mem1, spk1, b1, tau_m1, tau_adp1, mem1n, spk1n, b1n);

    {
        const long T = 2L * NB * NH1;
        convA8_kernel<<<(int)((T + 255) / 256), 256>>>(spk2, spk1n);
    }

    gemm2_i8_kernel<<<dim3(32, 16, 2), 256, SMEM_I8>>>(
        spk2, mem2, b2, mem2n, spk2n, b2n);

    head_kernel<<<NB, 320>>>(spk2n, mem_out, out_tau_m, log_sm, mem_out_n);
}

// round 6
// speedup vs baseline: 2.1362x; 2.1362x over previous
#include <cuda_runtime.h>
#include <cuda_fp16.h>
#include <cstdint>

// Problem dims
#define NB    4096
#define IN_D  1024
#define NH0   4000
#define NH1   4000
#define NR    2000
#define NOUT  10
#define KP0   4096      // padded K, out-half  ([spk_out|pad][spk_in|pad])
#define KP1   8192      // padded K, in-half   (+ [spk1n|pad])
#define NPAD  2048

#define BASE_THRE 0.1f
#define R_M       3.0f
#define BETA      1.8f

#define SC1   2.44140625e-4f   // 2^-12 fold scale for second fp16 term

// ---------------------------------------------------------------------------
// Static device scratch (zero-initialized; pad regions stay zero forever)
// ---------------------------------------------------------------------------
__device__ __align__(256) __half g_Wo[2][(size_t)NPAD * KP0];
__device__ __align__(256) __half g_Wi[2][(size_t)NPAD * KP1];
__device__ __align__(256) __half g_Ah[(size_t)NB * KP1];
__device__ float g_stm2[NH1];
__device__ float g_sta2[NH1];
__device__ float g_bias2[NH1];

__device__ __forceinline__ float sigm(float x) { return 1.0f / (1.0f + expf(-x)); }

__device__ __forceinline__ uint32_t smem_u32(const void* p) {
    uint32_t a;
    asm("{ .reg .u64 t; cvta.to.shared.u64 t, %1; cvt.u32.u64 %0, t; }" : "=r"(a) : "l"(p));
    return a;
}
__device__ __forceinline__ void cp16(uint32_t dst, const void* src) {
    asm volatile("cp.async.cg.shared.global [%0], [%1], 16;" :: "r"(dst), "l"(src) : "memory");
}
#define CP_COMMIT() asm volatile("cp.async.commit_group;" ::: "memory")
#define CP_WAIT2()  asm volatile("cp.async.wait_group 2;" ::: "memory")

__device__ __forceinline__ void ldm_x4(uint32_t& r0, uint32_t& r1, uint32_t& r2, uint32_t& r3,
                                       uint32_t addr) {
    asm volatile("ldmatrix.sync.aligned.m8n8.x4.shared.b16 {%0,%1,%2,%3}, [%4];"
                 : "=r"(r0), "=r"(r1), "=r"(r2), "=r"(r3) : "r"(addr));
}
__device__ __forceinline__ void hmma16816(float* c, const uint32_t* a, uint32_t b0, uint32_t b1) {
    asm volatile(
        "mma.sync.aligned.m16n8k16.row.col.f32.f16.f16.f32 "
        "{%0,%1,%2,%3}, {%4,%5,%6,%7}, {%8,%9}, {%0,%1,%2,%3};"
        : "+f"(c[0]), "+f"(c[1]), "+f"(c[2]), "+f"(c[3])
        : "r"(a[0]), "r"(a[1]), "r"(a[2]), "r"(a[3]), "r"(b0), "r"(b1));
}

// 2-term fp16 split: w = h0 + h1 * 2^-12   (h1 scaled into normal range)
__device__ __forceinline__ void split2h(float w, __half& h0, __half& h1) {
    h0 = __float2half(w);
    float r = w - __half2float(h0);
    h1 = __float2half(r * 4096.0f);
}

// ---------------------------------------------------------------------------
// Weight conversion: fp32 -> 2 fp16 planes, packed K layout; col params
// ---------------------------------------------------------------------------
__global__ void convW_kernel(
    const float* __restrict__ rec4out, const float* __restrict__ in2out,
    const float* __restrict__ out2in,  const float* __restrict__ rec4in,
    const float* __restrict__ x2in,
    const float* __restrict__ tau_m2,  const float* __restrict__ tau_adp2,
    const float* __restrict__ rec4out_b, const float* __restrict__ in2out_b,
    const float* __restrict__ out2in_b,  const float* __restrict__ rec4in_b,
    const float* __restrict__ x2in_b)
{
    const long S1 = (long)NR * NR;
    const long S2 = (long)NR * NH0;
    long i = (long)blockIdx.x * blockDim.x + threadIdx.x;
    if (i < 4 * S1) {
        int sel = (int)(i / S1);
        long r  = i % S1;
        int n = (int)(r / NR), k = (int)(r % NR);
        float w; size_t dst; int which;
        if (sel == 0)      { w = rec4out[r]; dst = (size_t)n * KP0 + k;        which = 0; }
        else if (sel == 1) { w = in2out[r];  dst = (size_t)n * KP0 + 2048 + k; which = 0; }
        else if (sel == 2) { w = out2in[r];  dst = (size_t)n * KP1 + k;        which = 1; }
        else               { w = rec4in[r];  dst = (size_t)n * KP1 + 2048 + k; which = 1; }
        __half a, b; split2h(w, a, b);
        if (which == 0) { g_Wo[0][dst] = a; g_Wo[1][dst] = b; }
        else            { g_Wi[0][dst] = a; g_Wi[1][dst] = b; }
    } else if (i < 4 * S1 + S2) {
        long r = i - 4 * S1;
        int n = (int)(r / NH0), k = (int)(r % NH0);
        __half a, b; split2h(x2in[r], a, b);
        size_t dst = (size_t)n * KP1 + 4096 + k;
        g_Wi[0][dst] = a; g_Wi[1][dst] = b;
    } else if (i < 4 * S1 + S2 + NH1) {
        int g = (int)(i - 4 * S1 - S2);
        g_stm2[g] = sigm(tau_m2[g]);
        g_sta2[g] = sigm(tau_adp2[g]);
        g_bias2[g] = (g < NR) ? (rec4out_b[g] + in2out_b[g])
                              : (x2in_b[g - NR] + rec4in_b[g - NR] + out2in_b[g - NR]);
    }
}

// Pack spikes (exact {0,1} in fp16): [spk_out|0][spk_in|0][spk1n|0]
__global__ void convA_kernel(const float* __restrict__ spk2, const float* __restrict__ spk1n)
{
    const long T1 = (long)NB * NH1;
    long i = (long)blockIdx.x * blockDim.x + threadIdx.x;
    if (i < T1) {
        int b = (int)(i / NH1), k = (int)(i % NH1);
        g_Ah[(size_t)b * KP1 + (k < NR ? k : k + 48)] = __float2half(spk2[i]);
    } else if (i < 2 * T1) {
        long r = i - T1;
        int b = (int)(r / NH0), k = (int)(r % NH0);
        g_Ah[(size_t)b * KP1 + 4096 + k] = __float2half(spk1n[r]);
    }
}

// ---------------------------------------------------------------------------
// GEMM2 via HMMA fp16 (2-term split, dual accumulators), CTA tile 128x64,
// BK=32, 4-stage cp.async, 2 CTAs/SM.  grid: (32 m, 32 n, 2 modes), 256 thr.
// Warp layout: 8 warps as 4(m) x 2(n), warp tile 32x32 (mi=2, ni=4).
// SMEM/stage: A 128x80B + 2 W-term tiles 64x80B = 20480B; 4 stages = 80KB.
// ---------------------------------------------------------------------------
#define ROWB   80
#define ATILE  (128 * ROWB)          // 10240
#define BTILE  (64 * ROWB)           // 5120
#define STG    (ATILE + 2 * BTILE)   // 20480
#define SMEM_G2 (4 * STG)            // 81920

__global__ void __launch_bounds__(256, 2) gemm2_h2_kernel(
    const float* __restrict__ spk2, const float* __restrict__ mem2,
    const float* __restrict__ b2,
    float* __restrict__ out_mem2, float* __restrict__ out_spk2, float* __restrict__ out_b2)
{
    extern __shared__ char smem[];
    const uint32_t sb = smem_u32(smem);
    const int tid  = threadIdx.x;
    const int wid  = tid >> 5;
    const int lane = tid & 31;
    const int mode = blockIdx.z;
    const int m0   = blockIdx.x * 128;
    const int n0   = blockIdx.y * 64;          // local column within half

    const int Kpad = mode ? KP1 : KP0;
    const int C    = Kpad / 32;
    const __half* A0 = g_Ah + (size_t)m0 * KP1;
    const __half* W0 = (mode ? &g_Wi[0][0] : &g_Wo[0][0]) + (size_t)n0 * Kpad;
    const __half* W1 = (mode ? &g_Wi[1][0] : &g_Wo[1][0]) + (size_t)n0 * Kpad;

    // loader: A -> 128 rows x 4 chunks(16B): row=tid>>1, chunks 2*(tid&1)+{0,1}
    //         B -> term=tid>>7, row=(tid>>1)&63, chunks 2*(tid&1)+{0,1}
    const int arow = tid >> 1;
    const int ach  = (tid & 1) * 2;
    const int bt   = tid >> 7;
    const int brow = (tid >> 1) & 63;
    const __half* Wsel = bt ? W1 : W0;

    auto issue = [&](int c) {
        const uint32_t dst = sb + (c & 3) * STG;
        const size_t ko = (size_t)c * 32;
        #pragma unroll
        for (int j = 0; j < 2; j++) {
            cp16(dst + arow * ROWB + (ach + j) * 16,
                 A0 + (size_t)arow * KP1 + ko + (ach + j) * 8);
            cp16(dst + ATILE + bt * BTILE + brow * ROWB + (ach + j) * 16,
                 Wsel + (size_t)brow * Kpad + ko + (ach + j) * 8);
        }
        CP_COMMIT();
    };

    const int wm = wid >> 1;     // 0..3
    const int wn = wid & 1;      // 0..1
    const int lrow = lane & 15;
    const int lcol = (lane >> 4) * 16;

    float acc0[2][4][4], acc1[2][4][4];
    #pragma unroll
    for (int mi = 0; mi < 2; mi++)
        #pragma unroll
        for (int ni = 0; ni < 4; ni++)
            #pragma unroll
            for (int r = 0; r < 4; r++) { acc0[mi][ni][r] = 0.f; acc1[mi][ni][r] = 0.f; }

    issue(0); issue(1); issue(2);

    for (int c = 0; c < C; c++) {
        CP_WAIT2();
        __syncthreads();
        if (c + 3 < C) issue(c + 3);
        else CP_COMMIT();                  // keep group accounting consistent

        const uint32_t stb = sb + (c & 3) * STG;
        #pragma unroll
        for (int ks = 0; ks < 2; ks++) {
            uint32_t a[2][4];
            #pragma unroll
            for (int mi = 0; mi < 2; mi++) {
                const uint32_t ad = stb + (wm * 32 + mi * 16 + lrow) * ROWB + ks * 32 + lcol;
                ldm_x4(a[mi][0], a[mi][1], a[mi][2], a[mi][3], ad);
            }
            #pragma unroll
            for (int t = 0; t < 2; t++) {
                uint32_t b[4][2];
                #pragma unroll
                for (int nj = 0; nj < 2; nj++) {
                    uint32_t r0, r1, r2, r3;
                    const uint32_t bd = stb + ATILE + t * BTILE
                                      + (wn * 32 + nj * 16 + lrow) * ROWB + ks * 32 + lcol;
                    ldm_x4(r0, r1, r2, r3, bd);
                    b[nj * 2 + 0][0] = r0; b[nj * 2 + 0][1] = r2;
                    b[nj * 2 + 1][0] = r1; b[nj * 2 + 1][1] = r3;
                }
                float (*acc)[4][4] = t ? acc1 : acc0;
                #pragma unroll
                for (int mi = 0; mi < 2; mi++)
                    #pragma unroll
                    for (int ni = 0; ni < 4; ni++)
                        hmma16816(acc[mi][ni], a[mi], b[ni][0], b[ni][1]);
            }
        }
        __syncthreads();
    }

    // Epilogue: fused mem_update2; v = acc0 + 2^-12 * acc1 + bias
    const int erow = lane >> 2;
    const int ecol = (lane & 3) * 2;
    #pragma unroll
    for (int mi = 0; mi < 2; mi++) {
        #pragma unroll
        for (int r2i = 0; r2i < 2; r2i++) {
            const int m = m0 + wm * 32 + mi * 16 + erow + r2i * 8;
            const size_t rowo = (size_t)m * NH1;
            #pragma unroll
            for (int ni = 0; ni < 4; ni++) {
                #pragma unroll
                for (int cc = 0; cc < 2; cc++) {
                    const int nl = n0 + wn * 32 + ni * 8 + ecol + cc;
                    if (nl >= NR) continue;
                    const int g = mode * NR + nl;
                    const size_t idx = rowo + g;
                    const float v = acc0[mi][ni][r2i * 2 + cc]
                                  + SC1 * acc1[mi][ni][r2i * 2 + cc]
                                  + g_bias2[g];
                    const float tm = g_stm2[g], ta = g_sta2[g];
                    const float sp = spk2[idx];
                    const float bb = ta * b2[idx] + (1.f - ta) * sp;
                    const float thre = BASE_THRE + BETA * bb;
                    const float mem = mem2[idx] * tm + (1.f - tm) * R_M * v - thre * sp;
                    out_mem2[idx] = mem;
                    out_spk2[idx] = (mem - thre) > 0.f ? 1.f : 0.f;
                    out_b2[idx]   = bb;
                }
            }
        }
    }
}

// ---------------------------------------------------------------------------
// GEMM1 (fp32 FFMA, at roofline) — unchanged
// ---------------------------------------------------------------------------
__device__ __forceinline__ void gemm_seg(
    const float* __restrict__ A, int lda, int aoff,
    const float* __restrict__ Bm, int ldb, int K, int nmaxB,
    int m0, int n0, float* As, float* Bs, float acc[8][8])
{
    const int tid = threadIdx.x;
    const int ar = tid >> 2, ac = (tid & 3) << 2;
    const int ty = tid >> 4, tx = tid & 15;
    for (int k0 = 0; k0 < K; k0 += 16) {
        #pragma unroll
        for (int r = 0; r < 128; r += 64) {
            const float4 v = *(const float4*)(A + (size_t)(m0 + ar + r) * lda + (aoff + k0 + ac));
            As[(ac + 0) * 128 + ar + r] = v.x; As[(ac + 1) * 128 + ar + r] = v.y;
            As[(ac + 2) * 128 + ar + r] = v.z; As[(ac + 3) * 128 + ar + r] = v.w;
        }
        #pragma unroll
        for (int r = 0; r < 128; r += 64) {
            const int n = n0 + ar + r;
            float4 v = make_float4(0.f, 0.f, 0.f, 0.f);
            if (n < nmaxB) v = *(const float4*)(Bm + (size_t)n * ldb + (k0 + ac));
            Bs[(ac + 0) * 128 + ar + r] = v.x; Bs[(ac + 1) * 128 + ar + r] = v.y;
            Bs[(ac + 2) * 128 + ar + r] = v.z; Bs[(ac + 3) * 128 + ar + r] = v.w;
        }
        __syncthreads();
        #pragma unroll
        for (int kk = 0; kk < 16; kk++) {
            float a[8], b[8];
            #pragma unroll
            for (int i = 0; i < 8; i++) a[i] = As[kk * 128 + ty * 8 + i];
            #pragma unroll
            for (int j = 0; j < 8; j++) b[j] = Bs[kk * 128 + tx * 8 + j];
            #pragma unroll
            for (int i = 0; i < 8; i++)
                #pragma unroll
                for (int j = 0; j < 8; j++) acc[i][j] = fmaf(a[i], b[j], acc[i][j]);
        }
        __syncthreads();
    }
}

__global__ void __launch_bounds__(256, 2) gemm1_kernel(
    const float* __restrict__ x_t, const float* __restrict__ fc_w, const float* __restrict__ fc_b,
    const float* __restrict__ mem1, const float* __restrict__ spk1, const float* __restrict__ b1,
    const float* __restrict__ tau_m1, const float* __restrict__ tau_adp1,
    float* __restrict__ out_mem1, float* __restrict__ out_spk1, float* __restrict__ out_b1)
{
    __shared__ float As[16 * 128];
    __shared__ float Bs[16 * 128];
    const int n0 = blockIdx.x * 128, m0 = blockIdx.y * 128;
    float acc[8][8];
    #pragma unroll
    for (int i = 0; i < 8; i++)
        #pragma unroll
        for (int j = 0; j < 8; j++) acc[i][j] = 0.f;
    gemm_seg(x_t, IN_D, 0, fc_w, IN_D, IN_D, NH0, m0, n0, As, Bs, acc);
    const int ty = threadIdx.x >> 4, tx = threadIdx.x & 15;
    float tmv[8], tav[8], fbv[8];
    #pragma unroll
    for (int j = 0; j < 8; j++) {
        const int n = n0 + tx * 8 + j; const bool v = (n < NH0);
        tmv[j] = sigm(v ? tau_m1[n] : 0.f);
        tav[j] = sigm(v ? tau_adp1[n] : 0.f);
        fbv[j] = v ? fc_b[n] : 0.f;
    }
    #pragma unroll
    for (int i = 0; i < 8; i++) {
        const int m = m0 + ty * 8 + i;
        const size_t rowo = (size_t)m * NH0;
        #pragma unroll
        for (int j = 0; j < 8; j++) {
            const int n = n0 + tx * 8 + j;
            if (n >= NH0) continue;
            const size_t idx = rowo + n;
            const float sp = spk1[idx];
            const float bb = tav[j] * b1[idx] + (1.f - tav[j]) * sp;
            const float thre = BASE_THRE + BETA * bb;
            const float mem = mem1[idx] * tmv[j] + (1.f - tmv[j]) * R_M * (acc[i][j] + fbv[j])
                            - thre * sp;
            out_mem1[idx] = mem;
            out_spk1[idx] = (mem - thre) > 0.f ? 1.f : 0.f;
            out_b1[idx]   = bb;
        }
    }
}

// ---------------------------------------------------------------------------
// Head: pooling + mem_out update + log_softmax
// ---------------------------------------------------------------------------
__global__ void head_kernel(
    const float* __restrict__ spk2n, const float* __restrict__ mem_out,
    const float* __restrict__ out_tau_m,
    float* __restrict__ log_sm, float* __restrict__ mem_out_n)
{
    __shared__ float xo[NOUT];
    const int row = blockIdx.x;
    const int w = threadIdx.x >> 5, lane = threadIdx.x & 31;
    float s = 0.f;
    const float* p = spk2n + (size_t)row * NH1 + w * 200;
    for (int i = lane; i < 200; i += 32) s += p[i];
    #pragma unroll
    for (int o = 16; o > 0; o >>= 1) s += __shfl_down_sync(0xffffffffu, s, o);
    if (lane == 0) xo[w] = s;
    __syncthreads();
    if (threadIdx.x == 0) {
        float v[NOUT];
        float mx = -1e30f;
        #pragma unroll
        for (int o = 0; o < NOUT; o++) {
            const float m = mem_out[(size_t)row * NOUT + o];
            const float mo = m + (xo[o] - m) * sigm(out_tau_m[o]);
            v[o] = mo; mem_out_n[(size_t)row * NOUT + o] = mo;
            mx = fmaxf(mx, mo);
        }
        float se = 0.f;
        #pragma unroll
        for (int o = 0; o < NOUT; o++) se += expf(v[o] - mx);
        const float lse = mx + logf(se);
        #pragma unroll
        for (int o = 0; o < NOUT; o++) log_sm[(size_t)row * NOUT + o] = v[o] - lse;
    }
}

// ---------------------------------------------------------------------------
// Launch
// ---------------------------------------------------------------------------
extern "C" void kernel_launch(void* const* d_in, const int* in_sizes, int n_in,
                              void* d_out, int out_size)
{
    const float* x_t       = (const float*)d_in[0];
    const float* mem1      = (const float*)d_in[1];
    const float* spk1      = (const float*)d_in[2];
    const float* b1        = (const float*)d_in[3];
    const float* mem2      = (const float*)d_in[4];
    const float* spk2      = (const float*)d_in[5];
    const float* b2        = (const float*)d_in[6];
    const float* mem_out   = (const float*)d_in[7];
    const float* fc_w      = (const float*)d_in[8];
    const float* fc_b      = (const float*)d_in[9];
    const float* tau_adp1  = (const float*)d_in[10];
    const float* tau_m1    = (const float*)d_in[11];
    const float* x2in_w    = (const float*)d_in[12];
    const float* x2in_b    = (const float*)d_in[13];
    const float* rec4in_w  = (const float*)d_in[14];
    const float* rec4in_b  = (const float*)d_in[15];
    const float* in2out_w  = (const float*)d_in[16];
    const float* in2out_b  = (const float*)d_in[17];
    const float* rec4out_w = (const float*)d_in[18];
    const float* rec4out_b = (const float*)d_in[19];
    const float* out2in_w  = (const float*)d_in[20];
    const float* out2in_b  = (const float*)d_in[21];
    const float* tau_adp2  = (const float*)d_in[22];
    const float* tau_m2    = (const float*)d_in[23];
    const float* out_tau_m = (const float*)d_in[24];

    float* out = (float*)d_out;
    const size_t BH = (size_t)NB * NH0;
    float* log_sm    = out;
    float* mem1n     = out + (size_t)NB * NOUT;
    float* spk1n     = mem1n + BH;
    float* b1n       = spk1n + BH;
    float* mem2n     = b1n + BH;
    float* spk2n     = mem2n + BH;
    float* b2n       = spk2n + BH;
    float* mem_out_n = b2n + BH;

    cudaFuncSetAttribute(gemm2_h2_kernel, cudaFuncAttributeMaxDynamicSharedMemorySize,
                         SMEM_G2);

    // weight split can start immediately (independent of gemm1)
    {
        const long T = 4L * NR * NR + (long)NR * NH0 + NH1;
        convW_kernel<<<(int)((T + 255) / 256), 256>>>(
            rec4out_w, in2out_w, out2in_w, rec4in_w, x2in_w,
            tau_m2, tau_adp2, rec4out_b, in2out_b, out2in_b, rec4in_b, x2in_b);
    }

    gemm1_kernel<<<dim3(32, 32), 256>>>(
        x_t, fc_w, fc_b, mem1, spk1, b1, tau_m1, tau_adp1, mem1n, spk1n, b1n);

    {
        const long T = 2L * NB * NH1;
        convA_kernel<<<(int)((T + 255) / 256), 256>>>(spk2, spk1n);
    }

    gemm2_h2_kernel<<<dim3(32, 32, 2), 256, SMEM_G2>>>(
        spk2, mem2, b2, mem2n, spk2n, b2n);

    head_kernel<<<NB, 320>>>(spk2n, mem_out, out_tau_m, log_sm, mem_out_n);
}

// round 7
// speedup vs baseline: 2.5284x; 1.1836x over previous
#include <cuda_runtime.h>
#include <cuda_fp16.h>
#include <cstdint>

// Problem dims
#define NB    4096
#define IN_D  1024
#define NH0   4000
#define NH1   4000
#define NR    2000
#define NOUT  10
#define KP0   4096
#define KP1   8192
#define NPAD  2048
#define N1PAD 4096

#define BASE_THRE 0.1f
#define R_M       3.0f
#define BETA      1.8f

#define SC1   2.44140625e-4f   // 2^-12 fold scale

// ---------------------------------------------------------------------------
// Static device scratch (zero-initialized; pad regions stay zero forever)
// ---------------------------------------------------------------------------
__device__ __align__(256) __half g_Wo[2][(size_t)NPAD * KP0];
__device__ __align__(256) __half g_Wi[2][(size_t)NPAD * KP1];
__device__ __align__(256) __half g_Ah[(size_t)NB * KP1];
__device__ __align__(256) __half g_X[2][(size_t)NB * IN_D];      // x_t split
__device__ __align__(256) __half g_Wf[2][(size_t)N1PAD * IN_D];  // fc_w split
__device__ float g_stm2[NH1];
__device__ float g_sta2[NH1];
__device__ float g_bias2[NH1];

__device__ __forceinline__ float sigm(float x) { return 1.0f / (1.0f + expf(-x)); }

__device__ __forceinline__ uint32_t smem_u32(const void* p) {
    uint32_t a;
    asm("{ .reg .u64 t; cvta.to.shared.u64 t, %1; cvt.u32.u64 %0, t; }" : "=r"(a) : "l"(p));
    return a;
}
__device__ __forceinline__ void cp16(uint32_t dst, const void* src) {
    asm volatile("cp.async.cg.shared.global [%0], [%1], 16;" :: "r"(dst), "l"(src) : "memory");
}
#define CP_COMMIT() asm volatile("cp.async.commit_group;" ::: "memory")
#define CP_WAIT1()  asm volatile("cp.async.wait_group 1;" ::: "memory")
#define CP_WAIT2()  asm volatile("cp.async.wait_group 2;" ::: "memory")

__device__ __forceinline__ void ldm_x4(uint32_t& r0, uint32_t& r1, uint32_t& r2, uint32_t& r3,
                                       uint32_t addr) {
    asm volatile("ldmatrix.sync.aligned.m8n8.x4.shared.b16 {%0,%1,%2,%3}, [%4];"
                 : "=r"(r0), "=r"(r1), "=r"(r2), "=r"(r3) : "r"(addr));
}
__device__ __forceinline__ void hmma16816(float* c, const uint32_t* a, uint32_t b0, uint32_t b1) {
    asm volatile(
        "mma.sync.aligned.m16n8k16.row.col.f32.f16.f16.f32 "
        "{%0,%1,%2,%3}, {%4,%5,%6,%7}, {%8,%9}, {%0,%1,%2,%3};"
        : "+f"(c[0]), "+f"(c[1]), "+f"(c[2]), "+f"(c[3])
        : "r"(a[0]), "r"(a[1]), "r"(a[2]), "r"(a[3]), "r"(b0), "r"(b1));
}

// 2-term fp16 split: v = h0 + h1 * 2^-12   (h1 scaled into normal range)
__device__ __forceinline__ void split2h(float w, __half& h0, __half& h1) {
    h0 = __float2half(w);
    float r = w - __half2float(h0);
    h1 = __float2half(r * 4096.0f);
}

// ---------------------------------------------------------------------------
// Pre-conversion: all weight/activation splits + layer2 column params
// ---------------------------------------------------------------------------
__global__ void convPre_kernel(
    const float* __restrict__ rec4out, const float* __restrict__ in2out,
    const float* __restrict__ out2in,  const float* __restrict__ rec4in,
    const float* __restrict__ x2in,    const float* __restrict__ fc_w,
    const float* __restrict__ x_t,
    const float* __restrict__ tau_m2,  const float* __restrict__ tau_adp2,
    const float* __restrict__ rec4out_b, const float* __restrict__ in2out_b,
    const float* __restrict__ out2in_b,  const float* __restrict__ rec4in_b,
    const float* __restrict__ x2in_b)
{
    const long S1 = (long)NR * NR;          // 4M each, x4
    const long S2 = (long)NR * NH0;         // 8M
    const long SF = (long)NH0 * IN_D;       // 4.096M
    const long SX = (long)NB * IN_D;        // 4.194M
    long i = (long)blockIdx.x * blockDim.x + threadIdx.x;
    if (i < 4 * S1) {
        int sel = (int)(i / S1);
        long r  = i % S1;
        int n = (int)(r / NR), k = (int)(r % NR);
        float w; size_t dst; int which;
        if (sel == 0)      { w = rec4out[r]; dst = (size_t)n * KP0 + k;        which = 0; }
        else if (sel == 1) { w = in2out[r];  dst = (size_t)n * KP0 + 2048 + k; which = 0; }
        else if (sel == 2) { w = out2in[r];  dst = (size_t)n * KP1 + k;        which = 1; }
        else               { w = rec4in[r];  dst = (size_t)n * KP1 + 2048 + k; which = 1; }
        __half a, b; split2h(w, a, b);
        if (which == 0) { g_Wo[0][dst] = a; g_Wo[1][dst] = b; }
        else            { g_Wi[0][dst] = a; g_Wi[1][dst] = b; }
    } else if (i < 4 * S1 + S2) {
        long r = i - 4 * S1;
        int n = (int)(r / NH0), k = (int)(r % NH0);
        __half a, b; split2h(x2in[r], a, b);
        size_t dst = (size_t)n * KP1 + 4096 + k;
        g_Wi[0][dst] = a; g_Wi[1][dst] = b;
    } else if (i < 4 * S1 + S2 + SF) {
        long r = i - 4 * S1 - S2;
        __half a, b; split2h(fc_w[r], a, b);
        int n = (int)(r / IN_D), k = (int)(r % IN_D);
        size_t dst = (size_t)n * IN_D + k;
        g_Wf[0][dst] = a; g_Wf[1][dst] = b;
    } else if (i < 4 * S1 + S2 + SF + SX) {
        long r = i - 4 * S1 - S2 - SF;
        __half a, b; split2h(x_t[r], a, b);
        g_X[0][r] = a; g_X[1][r] = b;
    } else if (i < 4 * S1 + S2 + SF + SX + NH1) {
        int g = (int)(i - 4 * S1 - S2 - SF - SX);
        g_stm2[g] = sigm(tau_m2[g]);
        g_sta2[g] = sigm(tau_adp2[g]);
        g_bias2[g] = (g < NR) ? (rec4out_b[g] + in2out_b[g])
                              : (x2in_b[g - NR] + rec4in_b[g - NR] + out2in_b[g - NR]);
    }
}

// Pack spikes (exact {0,1} in fp16): [spk_out|0][spk_in|0][spk1n|0]
__global__ void convA_kernel(const float* __restrict__ spk2, const float* __restrict__ spk1n)
{
    const long T1 = (long)NB * NH1;
    long i = (long)blockIdx.x * blockDim.x + threadIdx.x;
    if (i < T1) {
        int b = (int)(i / NH1), k = (int)(i % NH1);
        g_Ah[(size_t)b * KP1 + (k < NR ? k : k + 48)] = __float2half(spk2[i]);
    } else if (i < 2 * T1) {
        long r = i - T1;
        int b = (int)(r / NH0), k = (int)(r % NH0);
        g_Ah[(size_t)b * KP1 + 4096 + k] = __float2half(spk1n[r]);
    }
}

#define ROWB   80
#define ATILE  (128 * ROWB)          // 10240
#define BTILE  (64 * ROWB)           // 5120

// ---------------------------------------------------------------------------
// GEMM1 via HMMA fp16 cross-split (3 passes: x0w0 -> acc0; x0w1+x1w0 -> accS)
// CTA tile 128x64, BK=32, 3-stage cp.async, 2 CTAs/SM. grid (32, 64), 256thr
// SMEM/stage: 2 A tiles + 2 B tiles = 30720B; 3 stages = 92160B.
// ---------------------------------------------------------------------------
#define STG1    (2 * ATILE + 2 * BTILE)   // 30720
#define SMEM_G1 (3 * STG1)                // 92160

__global__ void __launch_bounds__(256, 2) gemm1_h2_kernel(
    const float* __restrict__ fc_b,
    const float* __restrict__ mem1, const float* __restrict__ spk1, const float* __restrict__ b1,
    const float* __restrict__ tau_m1, const float* __restrict__ tau_adp1,
    float* __restrict__ out_mem1, float* __restrict__ out_spk1, float* __restrict__ out_b1)
{
    extern __shared__ char smem[];
    const uint32_t sb = smem_u32(smem);
    const int tid  = threadIdx.x;
    const int wid  = tid >> 5;
    const int lane = tid & 31;
    const int m0   = blockIdx.x * 128;
    const int n0   = blockIdx.y * 64;
    const int C    = IN_D / 32;              // 32 chunks

    const __half* X0 = &g_X[0][(size_t)m0 * IN_D];
    const __half* X1 = &g_X[1][(size_t)m0 * IN_D];
    const __half* W0 = &g_Wf[0][(size_t)n0 * IN_D];
    const __half* W1 = &g_Wf[1][(size_t)n0 * IN_D];

    const int arow = tid >> 1;
    const int ach  = (tid & 1) * 2;
    const int bt   = tid >> 7;
    const int brow = (tid >> 1) & 63;
    const __half* Wsel = bt ? W1 : W0;

    auto issue = [&](int c) {
        const uint32_t dst = sb + (c % 3) * STG1;
        const size_t ko = (size_t)c * 32;
        #pragma unroll
        for (int j = 0; j < 2; j++) {
            cp16(dst + arow * ROWB + (ach + j) * 16,
                 X0 + (size_t)arow * IN_D + ko + (ach + j) * 8);
            cp16(dst + ATILE + arow * ROWB + (ach + j) * 16,
                 X1 + (size_t)arow * IN_D + ko + (ach + j) * 8);
            cp16(dst + 2 * ATILE + bt * BTILE + brow * ROWB + (ach + j) * 16,
                 Wsel + (size_t)brow * IN_D + ko + (ach + j) * 8);
        }
        CP_COMMIT();
    };

    const int wm = wid >> 1;     // 0..3
    const int wn = wid & 1;      // 0..1
    const int lrow = lane & 15;
    const int lcol = (lane >> 4) * 16;

    float acc0[2][4][4], accS[2][4][4];
    #pragma unroll
    for (int mi = 0; mi < 2; mi++)
        #pragma unroll
        for (int ni = 0; ni < 4; ni++)
            #pragma unroll
            for (int r = 0; r < 4; r++) { acc0[mi][ni][r] = 0.f; accS[mi][ni][r] = 0.f; }

    issue(0); issue(1);

    for (int c = 0; c < C; c++) {
        CP_WAIT1();
        __syncthreads();
        if (c + 2 < C) issue(c + 2);
        else CP_COMMIT();

        const uint32_t stb = sb + (c % 3) * STG1;
        #pragma unroll
        for (int ks = 0; ks < 2; ks++) {
            uint32_t a0[2][4], a1[2][4];
            #pragma unroll
            for (int mi = 0; mi < 2; mi++) {
                const uint32_t off = (wm * 32 + mi * 16 + lrow) * ROWB + ks * 32 + lcol;
                ldm_x4(a0[mi][0], a0[mi][1], a0[mi][2], a0[mi][3], stb + off);
                ldm_x4(a1[mi][0], a1[mi][1], a1[mi][2], a1[mi][3], stb + ATILE + off);
            }
            uint32_t b0[4][2], b1[4][2];
            #pragma unroll
            for (int nj = 0; nj < 2; nj++) {
                const uint32_t off = (wn * 32 + nj * 16 + lrow) * ROWB + ks * 32 + lcol;
                uint32_t r0, r1, r2, r3;
                ldm_x4(r0, r1, r2, r3, stb + 2 * ATILE + off);
                b0[nj * 2 + 0][0] = r0; b0[nj * 2 + 0][1] = r2;
                b0[nj * 2 + 1][0] = r1; b0[nj * 2 + 1][1] = r3;
                ldm_x4(r0, r1, r2, r3, stb + 2 * ATILE + BTILE + off);
                b1[nj * 2 + 0][0] = r0; b1[nj * 2 + 0][1] = r2;
                b1[nj * 2 + 1][0] = r1; b1[nj * 2 + 1][1] = r3;
            }
            #pragma unroll
            for (int mi = 0; mi < 2; mi++)
                #pragma unroll
                for (int ni = 0; ni < 4; ni++) {
                    hmma16816(acc0[mi][ni], a0[mi], b0[ni][0], b0[ni][1]);
                    hmma16816(accS[mi][ni], a0[mi], b1[ni][0], b1[ni][1]);
                    hmma16816(accS[mi][ni], a1[mi], b0[ni][0], b0[ni][1]);
                }
        }
    }

    // Epilogue: fused mem_update1; inp = acc0 + 2^-12*accS + fc_b
    const int erow = lane >> 2;
    const int ecol = (lane & 3) * 2;
    #pragma unroll
    for (int mi = 0; mi < 2; mi++) {
        #pragma unroll
        for (int r2i = 0; r2i < 2; r2i++) {
            const int m = m0 + wm * 32 + mi * 16 + erow + r2i * 8;
            const size_t rowo = (size_t)m * NH0;
            #pragma unroll
            for (int ni = 0; ni < 4; ni++) {
                #pragma unroll
                for (int cc = 0; cc < 2; cc++) {
                    const int n = n0 + wn * 32 + ni * 8 + ecol + cc;
                    if (n >= NH0) continue;
                    const size_t idx = rowo + n;
                    const float inp = acc0[mi][ni][r2i * 2 + cc]
                                    + SC1 * accS[mi][ni][r2i * 2 + cc]
                                    + fc_b[n];
                    const float tm = sigm(tau_m1[n]), ta = sigm(tau_adp1[n]);
                    const float sp = spk1[idx];
                    const float bb = ta * b1[idx] + (1.f - ta) * sp;
                    const float thre = BASE_THRE + BETA * bb;
                    const float mem = mem1[idx] * tm + (1.f - tm) * R_M * inp - thre * sp;
                    out_mem1[idx] = mem;
                    out_spk1[idx] = (mem - thre) > 0.f ? 1.f : 0.f;
                    out_b1[idx]   = bb;
                }
            }
        }
    }
}

// ---------------------------------------------------------------------------
// GEMM2 via HMMA fp16 (2-term weight split), CTA tile 128x64, BK=32,
// 4-stage cp.async, 2 CTAs/SM.  grid: (32 m, 32 n, 2 modes), 256 thr.
// ---------------------------------------------------------------------------
#define STG     (ATILE + 2 * BTILE)   // 20480
#define SMEM_G2 (4 * STG)             // 81920

__global__ void __launch_bounds__(256, 2) gemm2_h2_kernel(
    const float* __restrict__ spk2, const float* __restrict__ mem2,
    const float* __restrict__ b2,
    float* __restrict__ out_mem2, float* __restrict__ out_spk2, float* __restrict__ out_b2)
{
    extern __shared__ char smem[];
    const uint32_t sb = smem_u32(smem);
    const int tid  = threadIdx.x;
    const int wid  = tid >> 5;
    const int lane = tid & 31;
    const int mode = blockIdx.z;
    const int m0   = blockIdx.x * 128;
    const int n0   = blockIdx.y * 64;

    const int Kpad = mode ? KP1 : KP0;
    const int C    = Kpad / 32;
    const __half* A0 = g_Ah + (size_t)m0 * KP1;
    const __half* W0 = (mode ? &g_Wi[0][0] : &g_Wo[0][0]) + (size_t)n0 * Kpad;
    const __half* W1 = (mode ? &g_Wi[1][0] : &g_Wo[1][0]) + (size_t)n0 * Kpad;

    const int arow = tid >> 1;
    const int ach  = (tid & 1) * 2;
    const int bt   = tid >> 7;
    const int brow = (tid >> 1) & 63;
    const __half* Wsel = bt ? W1 : W0;

    auto issue = [&](int c) {
        const uint32_t dst = sb + (c & 3) * STG;
        const size_t ko = (size_t)c * 32;
        #pragma unroll
        for (int j = 0; j < 2; j++) {
            cp16(dst + arow * ROWB + (ach + j) * 16,
                 A0 + (size_t)arow * KP1 + ko + (ach + j) * 8);
            cp16(dst + ATILE + bt * BTILE + brow * ROWB + (ach + j) * 16,
                 Wsel + (size_t)brow * Kpad + ko + (ach + j) * 8);
        }
        CP_COMMIT();
    };

    const int wm = wid >> 1;
    const int wn = wid & 1;
    const int lrow = lane & 15;
    const int lcol = (lane >> 4) * 16;

    float acc0[2][4][4], acc1[2][4][4];
    #pragma unroll
    for (int mi = 0; mi < 2; mi++)
        #pragma unroll
        for (int ni = 0; ni < 4; ni++)
            #pragma unroll
            for (int r = 0; r < 4; r++) { acc0[mi][ni][r] = 0.f; acc1[mi][ni][r] = 0.f; }

    issue(0); issue(1); issue(2);

    for (int c = 0; c < C; c++) {
        CP_WAIT2();
        __syncthreads();
        if (c + 3 < C) issue(c + 3);
        else CP_COMMIT();

        const uint32_t stb = sb + (c & 3) * STG;
        #pragma unroll
        for (int ks = 0; ks < 2; ks++) {
            uint32_t a[2][4];
            #pragma unroll
            for (int mi = 0; mi < 2; mi++) {
                const uint32_t ad = stb + (wm * 32 + mi * 16 + lrow) * ROWB + ks * 32 + lcol;
                ldm_x4(a[mi][0], a[mi][1], a[mi][2], a[mi][3], ad);
            }
            #pragma unroll
            for (int t = 0; t < 2; t++) {
                uint32_t b[4][2];
                #pragma unroll
                for (int nj = 0; nj < 2; nj++) {
                    uint32_t r0, r1, r2, r3;
                    const uint32_t bd = stb + ATILE + t * BTILE
                                      + (wn * 32 + nj * 16 + lrow) * ROWB + ks * 32 + lcol;
                    ldm_x4(r0, r1, r2, r3, bd);
                    b[nj * 2 + 0][0] = r0; b[nj * 2 + 0][1] = r2;
                    b[nj * 2 + 1][0] = r1; b[nj * 2 + 1][1] = r3;
                }
                float (*acc)[4][4] = t ? acc1 : acc0;
                #pragma unroll
                for (int mi = 0; mi < 2; mi++)
                    #pragma unroll
                    for (int ni = 0; ni < 4; ni++)
                        hmma16816(acc[mi][ni], a[mi], b[ni][0], b[ni][1]);
            }
        }
    }

    // Epilogue: fused mem_update2; v = acc0 + 2^-12 * acc1 + bias
    const int erow = lane >> 2;
    const int ecol = (lane & 3) * 2;
    #pragma unroll
    for (int mi = 0; mi < 2; mi++) {
        #pragma unroll
        for (int r2i = 0; r2i < 2; r2i++) {
            const int m = m0 + wm * 32 + mi * 16 + erow + r2i * 8;
            const size_t rowo = (size_t)m * NH1;
            #pragma unroll
            for (int ni = 0; ni < 4; ni++) {
                #pragma unroll
                for (int cc = 0; cc < 2; cc++) {
                    const int nl = n0 + wn * 32 + ni * 8 + ecol + cc;
                    if (nl >= NR) continue;
                    const int g = mode * NR + nl;
                    const size_t idx = rowo + g;
                    const float v = acc0[mi][ni][r2i * 2 + cc]
                                  + SC1 * acc1[mi][ni][r2i * 2 + cc]
                                  + g_bias2[g];
                    const float tm = g_stm2[g], ta = g_sta2[g];
                    const float sp = spk2[idx];
                    const float bb = ta * b2[idx] + (1.f - ta) * sp;
                    const float thre = BASE_THRE + BETA * bb;
                    const float mem = mem2[idx] * tm + (1.f - tm) * R_M * v - thre * sp;
                    out_mem2[idx] = mem;
                    out_spk2[idx] = (mem - thre) > 0.f ? 1.f : 0.f;
                    out_b2[idx]   = bb;
                }
            }
        }
    }
}

// ---------------------------------------------------------------------------
// Head: pooling + mem_out update + log_softmax
// ---------------------------------------------------------------------------
__global__ void head_kernel(
    const float* __restrict__ spk2n, const float* __restrict__ mem_out,
    const float* __restrict__ out_tau_m,
    float* __restrict__ log_sm, float* __restrict__ mem_out_n)
{
    __shared__ float xo[NOUT];
    const int row = blockIdx.x;
    const int w = threadIdx.x >> 5, lane = threadIdx.x & 31;
    float s = 0.f;
    const float* p = spk2n + (size_t)row * NH1 + w * 200;
    for (int i = lane; i < 200; i += 32) s += p[i];
    #pragma unroll
    for (int o = 16; o > 0; o >>= 1) s += __shfl_down_sync(0xffffffffu, s, o);
    if (lane == 0) xo[w] = s;
    __syncthreads();
    if (threadIdx.x == 0) {
        float v[NOUT];
        float mx = -1e30f;
        #pragma unroll
        for (int o = 0; o < NOUT; o++) {
            const float m = mem_out[(size_t)row * NOUT + o];
            const float mo = m + (xo[o] - m) * sigm(out_tau_m[o]);
            v[o] = mo; mem_out_n[(size_t)row * NOUT + o] = mo;
            mx = fmaxf(mx, mo);
        }
        float se = 0.f;
        #pragma unroll
        for (int o = 0; o < NOUT; o++) se += expf(v[o] - mx);
        const float lse = mx + logf(se);
        #pragma unroll
        for (int o = 0; o < NOUT; o++) log_sm[(size_t)row * NOUT + o] = v[o] - lse;
    }
}

// ---------------------------------------------------------------------------
// Launch
// ---------------------------------------------------------------------------
extern "C" void kernel_launch(void* const* d_in, const int* in_sizes, int n_in,
                              void* d_out, int out_size)
{
    const float* x_t       = (const float*)d_in[0];
    const float* mem1      = (const float*)d_in[1];
    const float* spk1      = (const float*)d_in[2];
    const float* b1        = (const float*)d_in[3];
    const float* mem2      = (const float*)d_in[4];
    const float* spk2      = (const float*)d_in[5];
    const float* b2        = (const float*)d_in[6];
    const float* mem_out   = (const float*)d_in[7];
    const float* fc_w      = (const float*)d_in[8];
    const float* fc_b      = (const float*)d_in[9];
    const float* tau_adp1  = (const float*)d_in[10];
    const float* tau_m1    = (const float*)d_in[11];
    const float* x2in_w    = (const float*)d_in[12];
    const float* x2in_b    = (const float*)d_in[13];
    const float* rec4in_w  = (const float*)d_in[14];
    const float* rec4in_b  = (const float*)d_in[15];
    const float* in2out_w  = (const float*)d_in[16];
    const float* in2out_b  = (const float*)d_in[17];
    const float* rec4out_w = (const float*)d_in[18];
    const float* rec4out_b = (const float*)d_in[19];
    const float* out2in_w  = (const float*)d_in[20];
    const float* out2in_b  = (const float*)d_in[21];
    const float* tau_adp2  = (const float*)d_in[22];
    const float* tau_m2    = (const float*)d_in[23];
    const float* out_tau_m = (const float*)d_in[24];

    float* out = (float*)d_out;
    const size_t BH = (size_t)NB * NH0;
    float* log_sm    = out;
    float* mem1n     = out + (size_t)NB * NOUT;
    float* spk1n     = mem1n + BH;
    float* b1n       = spk1n + BH;
    float* mem2n     = b1n + BH;
    float* spk2n     = mem2n + BH;
    float* b2n       = spk2n + BH;
    float* mem_out_n = b2n + BH;

    cudaFuncSetAttribute(gemm1_h2_kernel, cudaFuncAttributeMaxDynamicSharedMemorySize,
                         SMEM_G1);
    cudaFuncSetAttribute(gemm2_h2_kernel, cudaFuncAttributeMaxDynamicSharedMemorySize,
                         SMEM_G2);

    {
        const long T = 4L * NR * NR + (long)NR * NH0 + (long)NH0 * IN_D
                     + (long)NB * IN_D + NH1;
        convPre_kernel<<<(int)((T + 255) / 256), 256>>>(
            rec4out_w, in2out_w, out2in_w, rec4in_w, x2in_w, fc_w, x_t,
            tau_m2, tau_adp2, rec4out_b, in2out_b, out2in_b, rec4in_b, x2in_b);
    }

    gemm1_h2_kernel<<<dim3(32, 64), 256, SMEM_G1>>>(
        fc_b, mem1, spk1, b1, tau_m1, tau_adp1, mem1n, spk1n, b1n);

    {
        const long T = 2L * NB * NH1;
        convA_kernel<<<(int)((T + 255) / 256), 256>>>(spk2, spk1n);
    }

    gemm2_h2_kernel<<<dim3(32, 32, 2), 256, SMEM_G2>>>(
        spk2, mem2, b2, mem2n, spk2n, b2n);

    head_kernel<<<NB, 320>>>(spk2n, mem_out, out_tau_m, log_sm, mem_out_n);
}

// round 8
// speedup vs baseline: 2.6525x; 1.0491x over previous
#include <cuda_runtime.h>
#include <cuda_fp16.h>
#include <cstdint>

// Problem dims
#define NB    4096
#define IN_D  1024
#define NH0   4000
#define NH1   4000
#define NR    2000
#define NOUT  10
#define KP0   4096
#define KP1   8192
#define NPAD  2048
#define N1PAD 4096

#define BASE_THRE 0.1f
#define R_M       3.0f
#define BETA      1.8f

#define SC1   2.44140625e-4f   // 2^-12 fold scale

// ---------------------------------------------------------------------------
// Static device scratch (zero-initialized; pad regions stay zero forever)
// ---------------------------------------------------------------------------
__device__ __align__(256) __half g_Wo[2][(size_t)NPAD * KP0];
__device__ __align__(256) __half g_Wi[2][(size_t)NPAD * KP1];
__device__ __align__(256) __half g_Ah[(size_t)NB * KP1];
__device__ __align__(256) __half g_X[2][(size_t)NB * IN_D];
__device__ __align__(256) __half g_Wf[2][(size_t)N1PAD * IN_D];
__device__ float g_stm2[NH1];
__device__ float g_sta2[NH1];
__device__ float g_bias2[NH1];

__device__ __forceinline__ float sigm(float x) { return 1.0f / (1.0f + expf(-x)); }

__device__ __forceinline__ uint32_t smem_u32(const void* p) {
    uint32_t a;
    asm("{ .reg .u64 t; cvta.to.shared.u64 t, %1; cvt.u32.u64 %0, t; }" : "=r"(a) : "l"(p));
    return a;
}
__device__ __forceinline__ void cp16(uint32_t dst, const void* src) {
    asm volatile("cp.async.cg.shared.global [%0], [%1], 16;" :: "r"(dst), "l"(src) : "memory");
}
#define CP_COMMIT() asm volatile("cp.async.commit_group;" ::: "memory")
#define CP_WAIT2()  asm volatile("cp.async.wait_group 2;" ::: "memory")

__device__ __forceinline__ void ldm_x4(uint32_t& r0, uint32_t& r1, uint32_t& r2, uint32_t& r3,
                                       uint32_t addr) {
    asm volatile("ldmatrix.sync.aligned.m8n8.x4.shared.b16 {%0,%1,%2,%3}, [%4];"
                 : "=r"(r0), "=r"(r1), "=r"(r2), "=r"(r3) : "r"(addr));
}
__device__ __forceinline__ void hmma16816(float* c, const uint32_t* a, uint32_t b0, uint32_t b1) {
    asm volatile(
        "mma.sync.aligned.m16n8k16.row.col.f32.f16.f16.f32 "
        "{%0,%1,%2,%3}, {%4,%5,%6,%7}, {%8,%9}, {%0,%1,%2,%3};"
        : "+f"(c[0]), "+f"(c[1]), "+f"(c[2]), "+f"(c[3])
        : "r"(a[0]), "r"(a[1]), "r"(a[2]), "r"(a[3]), "r"(b0), "r"(b1));
}

__device__ __forceinline__ void split2h(float w, __half& h0, __half& h1) {
    h0 = __float2half(w);
    float r = w - __half2float(h0);
    h1 = __float2half(r * 4096.0f);
}

// ---------------------------------------------------------------------------
// Pre-conversion: all splits + layer2 column params
// ---------------------------------------------------------------------------
__global__ void convPre_kernel(
    const float* __restrict__ rec4out, const float* __restrict__ in2out,
    const float* __restrict__ out2in,  const float* __restrict__ rec4in,
    const float* __restrict__ x2in,    const float* __restrict__ fc_w,
    const float* __restrict__ x_t,
    const float* __restrict__ tau_m2,  const float* __restrict__ tau_adp2,
    const float* __restrict__ rec4out_b, const float* __restrict__ in2out_b,
    const float* __restrict__ out2in_b,  const float* __restrict__ rec4in_b,
    const float* __restrict__ x2in_b)
{
    const long S1 = (long)NR * NR;
    const long S2 = (long)NR * NH0;
    const long SF = (long)NH0 * IN_D;
    const long SX = (long)NB * IN_D;
    long i = (long)blockIdx.x * blockDim.x + threadIdx.x;
    if (i < 4 * S1) {
        int sel = (int)(i / S1);
        long r  = i % S1;
        int n = (int)(r / NR), k = (int)(r % NR);
        float w; size_t dst; int which;
        if (sel == 0)      { w = rec4out[r]; dst = (size_t)n * KP0 + k;        which = 0; }
        else if (sel == 1) { w = in2out[r];  dst = (size_t)n * KP0 + 2048 + k; which = 0; }
        else if (sel == 2) { w = out2in[r];  dst = (size_t)n * KP1 + k;        which = 1; }
        else               { w = rec4in[r];  dst = (size_t)n * KP1 + 2048 + k; which = 1; }
        __half a, b; split2h(w, a, b);
        if (which == 0) { g_Wo[0][dst] = a; g_Wo[1][dst] = b; }
        else            { g_Wi[0][dst] = a; g_Wi[1][dst] = b; }
    } else if (i < 4 * S1 + S2) {
        long r = i - 4 * S1;
        int n = (int)(r / NH0), k = (int)(r % NH0);
        __half a, b; split2h(x2in[r], a, b);
        size_t dst = (size_t)n * KP1 + 4096 + k;
        g_Wi[0][dst] = a; g_Wi[1][dst] = b;
    } else if (i < 4 * S1 + S2 + SF) {
        long r = i - 4 * S1 - S2;
        __half a, b; split2h(fc_w[r], a, b);
        g_Wf[0][r] = a; g_Wf[1][r] = b;
    } else if (i < 4 * S1 + S2 + SF + SX) {
        long r = i - 4 * S1 - S2 - SF;
        __half a, b; split2h(x_t[r], a, b);
        g_X[0][r] = a; g_X[1][r] = b;
    } else if (i < 4 * S1 + S2 + SF + SX + NH1) {
        int g = (int)(i - 4 * S1 - S2 - SF - SX);
        g_stm2[g] = sigm(tau_m2[g]);
        g_sta2[g] = sigm(tau_adp2[g]);
        g_bias2[g] = (g < NR) ? (rec4out_b[g] + in2out_b[g])
                              : (x2in_b[g - NR] + rec4in_b[g - NR] + out2in_b[g - NR]);
    }
}

// Pack spikes into fp16 A: [spk_out|0][spk_in|0][spk1n|0]
__global__ void convA_kernel(const float* __restrict__ spk2, const float* __restrict__ spk1n)
{
    const long T1 = (long)NB * NH1;
    long i = (long)blockIdx.x * blockDim.x + threadIdx.x;
    if (i < T1) {
        int b = (int)(i / NH1), k = (int)(i % NH1);
        g_Ah[(size_t)b * KP1 + (k < NR ? k : k + 48)] = __float2half(spk2[i]);
    } else if (i < 2 * T1) {
        long r = i - T1;
        int b = (int)(r / NH0), k = (int)(r % NH0);
        g_Ah[(size_t)b * KP1 + 4096 + k] = __float2half(spk1n[r]);
    }
}

#define ROWB   80
#define T128   (128 * ROWB)          // 10240 per 128-row tile

// ---------------------------------------------------------------------------
// GEMM1: HMMA cross-split (x0w0 -> acc0; x0w1+x1w0 -> accS)
// CTA 128x128, 512 thr (16 warps 4x4, warp tile 32x32), BK=32, 4 stages.
// Stage: A0,A1,B0,B1 each 128x80B = 40960B; 4 stages = 163840B.
// ---------------------------------------------------------------------------
#define STG1    (4 * T128)
#define SMEM_G1 (4 * STG1)

__global__ void __launch_bounds__(512, 1) gemm1_h2_kernel(
    const float* __restrict__ fc_b,
    const float* __restrict__ mem1, const float* __restrict__ spk1, const float* __restrict__ b1,
    const float* __restrict__ tau_m1, const float* __restrict__ tau_adp1,
    float* __restrict__ out_mem1, float* __restrict__ out_spk1, float* __restrict__ out_b1)
{
    extern __shared__ char smem[];
    const uint32_t sb = smem_u32(smem);
    const int tid  = threadIdx.x;
    const int wid  = tid >> 5;
    const int lane = tid & 31;
    const int m0   = blockIdx.x * 128;
    const int n0   = blockIdx.y * 128;
    const int C    = IN_D / 32;

    const __half* src[4] = {
        &g_X[0][(size_t)m0 * IN_D], &g_X[1][(size_t)m0 * IN_D],
        &g_Wf[0][(size_t)n0 * IN_D], &g_Wf[1][(size_t)n0 * IN_D] };

    // loader: 2048 cp16 per chunk, 4 per thread: i = tid + j*512
    auto issue = [&](int c) {
        const uint32_t dst = sb + (c & 3) * STG1;
        const size_t ko = (size_t)c * 32;
        #pragma unroll
        for (int j = 0; j < 4; j++) {
            const int i = tid + j * 512;
            const int row = i >> 2, ch = i & 3;     // row 0..511
            const int q = row >> 7, r = row & 127;
            cp16(dst + q * T128 + r * ROWB + ch * 16,
                 src[q] + (size_t)r * IN_D + ko + ch * 8);
        }
        CP_COMMIT();
    };

    const int wm = wid >> 2;     // 0..3
    const int wn = wid & 3;      // 0..3
    const int lrow = lane & 15;
    const int lcol = (lane >> 4) * 16;

    float acc0[2][4][4], accS[2][4][4];
    #pragma unroll
    for (int mi = 0; mi < 2; mi++)
        #pragma unroll
        for (int ni = 0; ni < 4; ni++)
            #pragma unroll
            for (int r = 0; r < 4; r++) { acc0[mi][ni][r] = 0.f; accS[mi][ni][r] = 0.f; }

    issue(0); issue(1); issue(2);

    for (int c = 0; c < C; c++) {
        CP_WAIT2();
        __syncthreads();
        if (c + 3 < C) issue(c + 3);
        else CP_COMMIT();

        const uint32_t stb = sb + (c & 3) * STG1;
        #pragma unroll
        for (int ks = 0; ks < 2; ks++) {
            uint32_t a0[2][4], a1[2][4];
            #pragma unroll
            for (int mi = 0; mi < 2; mi++) {
                const uint32_t off = (wm * 32 + mi * 16 + lrow) * ROWB + ks * 32 + lcol;
                ldm_x4(a0[mi][0], a0[mi][1], a0[mi][2], a0[mi][3], stb + off);
                ldm_x4(a1[mi][0], a1[mi][1], a1[mi][2], a1[mi][3], stb + T128 + off);
            }
            uint32_t b0[4][2], b1[4][2];
            #pragma unroll
            for (int nj = 0; nj < 2; nj++) {
                const uint32_t off = (wn * 32 + nj * 16 + lrow) * ROWB + ks * 32 + lcol;
                uint32_t r0, r1, r2, r3;
                ldm_x4(r0, r1, r2, r3, stb + 2 * T128 + off);
                b0[nj * 2 + 0][0] = r0; b0[nj * 2 + 0][1] = r2;
                b0[nj * 2 + 1][0] = r1; b0[nj * 2 + 1][1] = r3;
                ldm_x4(r0, r1, r2, r3, stb + 3 * T128 + off);
                b1[nj * 2 + 0][0] = r0; b1[nj * 2 + 0][1] = r2;
                b1[nj * 2 + 1][0] = r1; b1[nj * 2 + 1][1] = r3;
            }
            #pragma unroll
            for (int mi = 0; mi < 2; mi++)
                #pragma unroll
                for (int ni = 0; ni < 4; ni++) {
                    hmma16816(acc0[mi][ni], a0[mi], b0[ni][0], b0[ni][1]);
                    hmma16816(accS[mi][ni], a0[mi], b1[ni][0], b1[ni][1]);
                    hmma16816(accS[mi][ni], a1[mi], b0[ni][0], b0[ni][1]);
                }
        }
    }

    const int erow = lane >> 2;
    const int ecol = (lane & 3) * 2;
    #pragma unroll
    for (int mi = 0; mi < 2; mi++) {
        #pragma unroll
        for (int r2i = 0; r2i < 2; r2i++) {
            const int m = m0 + wm * 32 + mi * 16 + erow + r2i * 8;
            const size_t rowo = (size_t)m * NH0;
            #pragma unroll
            for (int ni = 0; ni < 4; ni++) {
                #pragma unroll
                for (int cc = 0; cc < 2; cc++) {
                    const int n = n0 + wn * 32 + ni * 8 + ecol + cc;
                    if (n >= NH0) continue;
                    const size_t idx = rowo + n;
                    const float inp = acc0[mi][ni][r2i * 2 + cc]
                                    + SC1 * accS[mi][ni][r2i * 2 + cc]
                                    + fc_b[n];
                    const float tm = sigm(tau_m1[n]), ta = sigm(tau_adp1[n]);
                    const float sp = spk1[idx];
                    const float bb = ta * b1[idx] + (1.f - ta) * sp;
                    const float thre = BASE_THRE + BETA * bb;
                    const float mem = mem1[idx] * tm + (1.f - tm) * R_M * inp - thre * sp;
                    out_mem1[idx] = mem;
                    out_spk1[idx] = (mem - thre) > 0.f ? 1.f : 0.f;
                    out_b1[idx]   = bb;
                }
            }
        }
    }
}

// ---------------------------------------------------------------------------
// GEMM2: HMMA 2-term weight split. CTA 128x128, 512 thr (16 warps 4x4,
// warp tile 32x32), BK=32, 4 stages.  grid: (32 m, 16 n, 2 modes)
// Stage: A(128x80) + B0,B1(128x80 each) = 30720B; 4 stages = 122880B.
// ---------------------------------------------------------------------------
#define STG2    (3 * T128)
#define SMEM_G2 (4 * STG2)

__global__ void __launch_bounds__(512, 1) gemm2_h2_kernel(
    const float* __restrict__ spk2, const float* __restrict__ mem2,
    const float* __restrict__ b2,
    float* __restrict__ out_mem2, float* __restrict__ out_spk2, float* __restrict__ out_b2)
{
    extern __shared__ char smem[];
    const uint32_t sb = smem_u32(smem);
    const int tid  = threadIdx.x;
    const int wid  = tid >> 5;
    const int lane = tid & 31;
    const int mode = blockIdx.z;
    const int m0   = blockIdx.x * 128;
    const int n0   = blockIdx.y * 128;

    const int Kpad = mode ? KP1 : KP0;
    const int C    = Kpad / 32;
    const __half* A0 = g_Ah + (size_t)m0 * KP1;
    const __half* W0 = (mode ? &g_Wi[0][0] : &g_Wo[0][0]) + (size_t)n0 * Kpad;
    const __half* W1 = (mode ? &g_Wi[1][0] : &g_Wo[1][0]) + (size_t)n0 * Kpad;

    // loader: 1536 cp16 per chunk, 3 per thread
    auto issue = [&](int c) {
        const uint32_t dst = sb + (c & 3) * STG2;
        const size_t ko = (size_t)c * 32;
        #pragma unroll
        for (int j = 0; j < 3; j++) {
            const int i = tid + j * 512;
            const int row = i >> 2, ch = i & 3;     // row 0..383
            if (row < 128) {
                cp16(dst + row * ROWB + ch * 16, A0 + (size_t)row * KP1 + ko + ch * 8);
            } else {
                const int t = (row - 128) >> 7, r = (row - 128) & 127;
                const __half* w = t ? W1 : W0;
                cp16(dst + (1 + t) * T128 + r * ROWB + ch * 16,
                     w + (size_t)r * Kpad + ko + ch * 8);
            }
        }
        CP_COMMIT();
    };

    const int wm = wid >> 2;
    const int wn = wid & 3;
    const int lrow = lane & 15;
    const int lcol = (lane >> 4) * 16;

    float acc0[2][4][4], acc1[2][4][4];
    #pragma unroll
    for (int mi = 0; mi < 2; mi++)
        #pragma unroll
        for (int ni = 0; ni < 4; ni++)
            #pragma unroll
            for (int r = 0; r < 4; r++) { acc0[mi][ni][r] = 0.f; acc1[mi][ni][r] = 0.f; }

    issue(0); issue(1); issue(2);

    for (int c = 0; c < C; c++) {
        CP_WAIT2();
        __syncthreads();
        if (c + 3 < C) issue(c + 3);
        else CP_COMMIT();

        const uint32_t stb = sb + (c & 3) * STG2;
        #pragma unroll
        for (int ks = 0; ks < 2; ks++) {
            uint32_t a[2][4];
            #pragma unroll
            for (int mi = 0; mi < 2; mi++) {
                const uint32_t ad = stb + (wm * 32 + mi * 16 + lrow) * ROWB + ks * 32 + lcol;
                ldm_x4(a[mi][0], a[mi][1], a[mi][2], a[mi][3], ad);
            }
            #pragma unroll
            for (int t = 0; t < 2; t++) {
                uint32_t b[4][2];
                #pragma unroll
                for (int nj = 0; nj < 2; nj++) {
                    uint32_t r0, r1, r2, r3;
                    const uint32_t bd = stb + (1 + t) * T128
                                      + (wn * 32 + nj * 16 + lrow) * ROWB + ks * 32 + lcol;
                    ldm_x4(r0, r1, r2, r3, bd);
                    b[nj * 2 + 0][0] = r0; b[nj * 2 + 0][1] = r2;
                    b[nj * 2 + 1][0] = r1; b[nj * 2 + 1][1] = r3;
                }
                float (*acc)[4][4] = t ? acc1 : acc0;
                #pragma unroll
                for (int mi = 0; mi < 2; mi++)
                    #pragma unroll
                    for (int ni = 0; ni < 4; ni++)
                        hmma16816(acc[mi][ni], a[mi], b[ni][0], b[ni][1]);
            }
        }
    }

    const int erow = lane >> 2;
    const int ecol = (lane & 3) * 2;
    #pragma unroll
    for (int mi = 0; mi < 2; mi++) {
        #pragma unroll
        for (int r2i = 0; r2i < 2; r2i++) {
            const int m = m0 + wm * 32 + mi * 16 + erow + r2i * 8;
            const size_t rowo = (size_t)m * NH1;
            #pragma unroll
            for (int ni = 0; ni < 4; ni++) {
                #pragma unroll
                for (int cc = 0; cc < 2; cc++) {
                    const int nl = n0 + wn * 32 + ni * 8 + ecol + cc;
                    if (nl >= NR) continue;
                    const int g = mode * NR + nl;
                    const size_t idx = rowo + g;
                    const float v = acc0[mi][ni][r2i * 2 + cc]
                                  + SC1 * acc1[mi][ni][r2i * 2 + cc]
                                  + g_bias2[g];
                    const float tm = g_stm2[g], ta = g_sta2[g];
                    const float sp = spk2[idx];
                    const float bb = ta * b2[idx] + (1.f - ta) * sp;
                    const float thre = BASE_THRE + BETA * bb;
                    const float mem = mem2[idx] * tm + (1.f - tm) * R_M * v - thre * sp;
                    out_mem2[idx] = mem;
                    out_spk2[idx] = (mem - thre) > 0.f ? 1.f : 0.f;
                    out_b2[idx]   = bb;
                }
            }
        }
    }
}

// ---------------------------------------------------------------------------
// Head: pooling + mem_out update + log_softmax
// ---------------------------------------------------------------------------
__global__ void head_kernel(
    const float* __restrict__ spk2n, const float* __restrict__ mem_out,
    const float* __restrict__ out_tau_m,
    float* __restrict__ log_sm, float* __restrict__ mem_out_n)
{
    __shared__ float xo[NOUT];
    const int row = blockIdx.x;
    const int w = threadIdx.x >> 5, lane = threadIdx.x & 31;
    float s = 0.f;
    const float* p = spk2n + (size_t)row * NH1 + w * 200;
    for (int i = lane; i < 200; i += 32) s += p[i];
    #pragma unroll
    for (int o = 16; o > 0; o >>= 1) s += __shfl_down_sync(0xffffffffu, s, o);
    if (lane == 0) xo[w] = s;
    __syncthreads();
    if (threadIdx.x == 0) {
        float v[NOUT];
        float mx = -1e30f;
        #pragma unroll
        for (int o = 0; o < NOUT; o++) {
            const float m = mem_out[(size_t)row * NOUT + o];
            const float mo = m + (xo[o] - m) * sigm(out_tau_m[o]);
            v[o] = mo; mem_out_n[(size_t)row * NOUT + o] = mo;
            mx = fmaxf(mx, mo);
        }
        float se = 0.f;
        #pragma unroll
        for (int o = 0; o < NOUT; o++) se += expf(v[o] - mx);
        const float lse = mx + logf(se);
        #pragma unroll
        for (int o = 0; o < NOUT; o++) log_sm[(size_t)row * NOUT + o] = v[o] - lse;
    }
}

// ---------------------------------------------------------------------------
// Launch
// ---------------------------------------------------------------------------
extern "C" void kernel_launch(void* const* d_in, const int* in_sizes, int n_in,
                              void* d_out, int out_size)
{
    const float* x_t       = (const float*)d_in[0];
    const float* mem1      = (const float*)d_in[1];
    const float* spk1      = (const float*)d_in[2];
    const float* b1        = (const float*)d_in[3];
    const float* mem2      = (const float*)d_in[4];
    const float* spk2      = (const float*)d_in[5];
    const float* b2        = (const float*)d_in[6];
    const float* mem_out   = (const float*)d_in[7];
    const float* fc_w      = (const float*)d_in[8];
    const float* fc_b      = (const float*)d_in[9];
    const float* tau_adp1  = (const float*)d_in[10];
    const float* tau_m1    = (const float*)d_in[11];
    const float* x2in_w    = (const float*)d_in[12];
    const float* x2in_b    = (const float*)d_in[13];
    const float* rec4in_w  = (const float*)d_in[14];
    const float* rec4in_b  = (const float*)d_in[15];
    const float* in2out_w  = (const float*)d_in[16];
    const float* in2out_b  = (const float*)d_in[17];
    const float* rec4out_w = (const float*)d_in[18];
    const float* rec4out_b = (const float*)d_in[19];
    const float* out2in_w  = (const float*)d_in[20];
    const float* out2in_b  = (const float*)d_in[21];
    const float* tau_adp2  = (const float*)d_in[22];
    const float* tau_m2    = (const float*)d_in[23];
    const float* out_tau_m = (const float*)d_in[24];

    float* out = (float*)d_out;
    const size_t BH = (size_t)NB * NH0;
    float* log_sm    = out;
    float* mem1n     = out + (size_t)NB * NOUT;
    float* spk1n     = mem1n + BH;
    float* b1n       = spk1n + BH;
    float* mem2n     = b1n + BH;
    float* spk2n     = mem2n + BH;
    float* b2n       = spk2n + BH;
    float* mem_out_n = b2n + BH;

    cudaFuncSetAttribute(gemm1_h2_kernel, cudaFuncAttributeMaxDynamicSharedMemorySize,
                         SMEM_G1);
    cudaFuncSetAttribute(gemm2_h2_kernel, cudaFuncAttributeMaxDynamicSharedMemorySize,
                         SMEM_G2);

    {
        const long T = 4L * NR * NR + (long)NR * NH0 + (long)NH0 * IN_D
                     + (long)NB * IN_D + NH1;
        convPre_kernel<<<(int)((T + 255) / 256), 256>>>(
            rec4out_w, in2out_w, out2in_w, rec4in_w, x2in_w, fc_w, x_t,
            tau_m2, tau_adp2, rec4out_b, in2out_b, out2in_b, rec4in_b, x2in_b);
    }

    gemm1_h2_kernel<<<dim3(32, 32), 512, SMEM_G1>>>(
        fc_b, mem1, spk1, b1, tau_m1, tau_adp1, mem1n, spk1n, b1n);

    {
        const long T = 2L * NB * NH1;
        convA_kernel<<<(int)((T + 255) / 256), 256>>>(spk2, spk1n);
    }

    gemm2_h2_kernel<<<dim3(32, 16, 2), 512, SMEM_G2>>>(
        spk2, mem2, b2, mem2n, spk2n, b2n);

    head_kernel<<<NB, 320>>>(spk2n, mem_out, out_tau_m, log_sm, mem_out_n);
}

// round 9
// speedup vs baseline: 3.3103x; 1.2480x over previous
#include <cuda_runtime.h>
#include <cuda_fp16.h>
#include <cstdint>

// Problem dims
#define NB    4096
#define IN_D  1024
#define NH0   4000
#define NH1   4000
#define NR    2000
#define NOUT  10
#define KP0   4096
#define KP1   8192
#define NPAD  2048
#define N1PAD 4096

#define BASE_THRE 0.1f
#define R_M       3.0f
#define BETA      1.8f

#define SC1   2.44140625e-4f   // 2^-12 fold scale

// ---------------------------------------------------------------------------
// Static device scratch (zero-initialized; pad regions stay zero forever)
// ---------------------------------------------------------------------------
__device__ __align__(256) __half g_Wo[2][(size_t)NPAD * KP0];
__device__ __align__(256) __half g_Wi[2][(size_t)NPAD * KP1];
__device__ __align__(256) __half g_Ah[(size_t)NB * KP1];
__device__ __align__(256) __half g_X[2][(size_t)NB * IN_D];
__device__ __align__(256) __half g_Wf[2][(size_t)N1PAD * IN_D];
__device__ float g_stm2[NH1];
__device__ float g_sta2[NH1];
__device__ float g_bias2[NH1];

__device__ __forceinline__ float sigm(float x) { return 1.0f / (1.0f + expf(-x)); }

__device__ __forceinline__ uint32_t smem_u32(const void* p) {
    uint32_t a;
    asm("{ .reg .u64 t; cvta.to.shared.u64 t, %1; cvt.u32.u64 %0, t; }" : "=r"(a) : "l"(p));
    return a;
}
__device__ __forceinline__ void cp16(uint32_t dst, const void* src) {
    asm volatile("cp.async.cg.shared.global [%0], [%1], 16;" :: "r"(dst), "l"(src) : "memory");
}
#define CP_COMMIT() asm volatile("cp.async.commit_group;" ::: "memory")
#define CP_WAIT1()  asm volatile("cp.async.wait_group 1;" ::: "memory")
#define CP_WAIT2()  asm volatile("cp.async.wait_group 2;" ::: "memory")

__device__ __forceinline__ void ldm_x4(uint32_t& r0, uint32_t& r1, uint32_t& r2, uint32_t& r3,
                                       uint32_t addr) {
    asm volatile("ldmatrix.sync.aligned.m8n8.x4.shared.b16 {%0,%1,%2,%3}, [%4];"
                 : "=r"(r0), "=r"(r1), "=r"(r2), "=r"(r3) : "r"(addr));
}
__device__ __forceinline__ void hmma16816(float* c, const uint32_t* a, uint32_t b0, uint32_t b1) {
    asm volatile(
        "mma.sync.aligned.m16n8k16.row.col.f32.f16.f16.f32 "
        "{%0,%1,%2,%3}, {%4,%5,%6,%7}, {%8,%9}, {%0,%1,%2,%3};"
        : "+f"(c[0]), "+f"(c[1]), "+f"(c[2]), "+f"(c[3])
        : "r"(a[0]), "r"(a[1]), "r"(a[2]), "r"(a[3]), "r"(b0), "r"(b1));
}

__device__ __forceinline__ void split2h(float w, __half& h0, __half& h1) {
    h0 = __float2half(w);
    float r = w - __half2float(h0);
    h1 = __float2half(r * 4096.0f);
}

// XOR-swizzled tile offset: 128 rows x 128B (8 chunks of 16B), conflict-free
__device__ __forceinline__ uint32_t sw(int row, int ch) {
    return (uint32_t)(row * 128 + ((ch ^ (row & 7)) << 4));
}

// ---------------------------------------------------------------------------
// Pre-conversion: all splits + layer2 column params
// ---------------------------------------------------------------------------
__global__ void convPre_kernel(
    const float* __restrict__ rec4out, const float* __restrict__ in2out,
    const float* __restrict__ out2in,  const float* __restrict__ rec4in,
    const float* __restrict__ x2in,    const float* __restrict__ fc_w,
    const float* __restrict__ x_t,
    const float* __restrict__ tau_m2,  const float* __restrict__ tau_adp2,
    const float* __restrict__ rec4out_b, const float* __restrict__ in2out_b,
    const float* __restrict__ out2in_b,  const float* __restrict__ rec4in_b,
    const float* __restrict__ x2in_b)
{
    const long S1 = (long)NR * NR;
    const long S2 = (long)NR * NH0;
    const long SF = (long)NH0 * IN_D;
    const long SX = (long)NB * IN_D;
    long i = (long)blockIdx.x * blockDim.x + threadIdx.x;
    if (i < 4 * S1) {
        int sel = (int)(i / S1);
        long r  = i % S1;
        int n = (int)(r / NR), k = (int)(r % NR);
        float w; size_t dst; int which;
        if (sel == 0)      { w = rec4out[r]; dst = (size_t)n * KP0 + k;        which = 0; }
        else if (sel == 1) { w = in2out[r];  dst = (size_t)n * KP0 + 2048 + k; which = 0; }
        else if (sel == 2) { w = out2in[r];  dst = (size_t)n * KP1 + k;        which = 1; }
        else               { w = rec4in[r];  dst = (size_t)n * KP1 + 2048 + k; which = 1; }
        __half a, b; split2h(w, a, b);
        if (which == 0) { g_Wo[0][dst] = a; g_Wo[1][dst] = b; }
        else            { g_Wi[0][dst] = a; g_Wi[1][dst] = b; }
    } else if (i < 4 * S1 + S2) {
        long r = i - 4 * S1;
        int n = (int)(r / NH0), k = (int)(r % NH0);
        __half a, b; split2h(x2in[r], a, b);
        size_t dst = (size_t)n * KP1 + 4096 + k;
        g_Wi[0][dst] = a; g_Wi[1][dst] = b;
    } else if (i < 4 * S1 + S2 + SF) {
        long r = i - 4 * S1 - S2;
        __half a, b; split2h(fc_w[r], a, b);
        g_Wf[0][r] = a; g_Wf[1][r] = b;
    } else if (i < 4 * S1 + S2 + SF + SX) {
        long r = i - 4 * S1 - S2 - SF;
        __half a, b; split2h(x_t[r], a, b);
        g_X[0][r] = a; g_X[1][r] = b;
    } else if (i < 4 * S1 + S2 + SF + SX + NH1) {
        int g = (int)(i - 4 * S1 - S2 - SF - SX);
        g_stm2[g] = sigm(tau_m2[g]);
        g_sta2[g] = sigm(tau_adp2[g]);
        g_bias2[g] = (g < NR) ? (rec4out_b[g] + in2out_b[g])
                              : (x2in_b[g - NR] + rec4in_b[g - NR] + out2in_b[g - NR]);
    }
}

// Pack spikes into fp16 A: [spk_out|0][spk_in|0][spk1n|0]
__global__ void convA_kernel(const float* __restrict__ spk2, const float* __restrict__ spk1n)
{
    const long T1 = (long)NB * NH1;
    long i = (long)blockIdx.x * blockDim.x + threadIdx.x;
    if (i < T1) {
        int b = (int)(i / NH1), k = (int)(i % NH1);
        g_Ah[(size_t)b * KP1 + (k < NR ? k : k + 48)] = __float2half(spk2[i]);
    } else if (i < 2 * T1) {
        long r = i - T1;
        int b = (int)(r / NH0), k = (int)(r % NH0);
        g_Ah[(size_t)b * KP1 + 4096 + k] = __float2half(spk1n[r]);
    }
}

#define TSZ 16384   // tile bytes: 128 rows x 128B (BK=64 fp16)

// ---------------------------------------------------------------------------
// GEMM1: HMMA cross-split (x0w0 -> acc0; x0w1+x1w0 -> accS)
// CTA 128x128, 512 thr (16 warps 4x4), BK=64, 3 stages, XOR swizzle.
// Stage: X0,X1,W0,W1 each 16KB = 64KB; 3 stages = 192KB.
// ---------------------------------------------------------------------------
#define STG1    (4 * TSZ)
#define SMEM_G1 (3 * STG1)

__global__ void __launch_bounds__(512, 1) gemm1_h2_kernel(
    const float* __restrict__ fc_b,
    const float* __restrict__ mem1, const float* __restrict__ spk1, const float* __restrict__ b1,
    const float* __restrict__ tau_m1, const float* __restrict__ tau_adp1,
    float* __restrict__ out_mem1, float* __restrict__ out_spk1, float* __restrict__ out_b1)
{
    extern __shared__ char smem[];
    const uint32_t sb = smem_u32(smem);
    const int tid  = threadIdx.x;
    const int wid  = tid >> 5;
    const int lane = tid & 31;
    const int m0   = blockIdx.x * 128;
    const int n0   = blockIdx.y * 128;
    const int C    = IN_D / 64;     // 16 chunks

    const __half* src[4] = {
        &g_X[0][(size_t)m0 * IN_D], &g_X[1][(size_t)m0 * IN_D],
        &g_Wf[0][(size_t)n0 * IN_D], &g_Wf[1][(size_t)n0 * IN_D] };

    // loader: 4096 cp16 per chunk, 8 per thread
    auto issue = [&](int c) {
        const uint32_t dst = sb + (c % 3) * STG1;
        const size_t ko = (size_t)c * 64;
        #pragma unroll
        for (int j = 0; j < 8; j++) {
            const int i = tid + j * 512;
            const int row = i >> 3, ch = i & 7;     // row 0..511
            const int q = row >> 7, r = row & 127;
            cp16(dst + q * TSZ + sw(r, ch),
                 src[q] + (size_t)r * IN_D + ko + ch * 8);
        }
        CP_COMMIT();
    };

    const int wm = wid >> 2;     // 0..3
    const int wn = wid & 3;      // 0..3
    const int lrow = lane & 15;
    const int lch  = lane >> 4;

    float acc0[2][4][4], accS[2][4][4];
    #pragma unroll
    for (int mi = 0; mi < 2; mi++)
        #pragma unroll
        for (int ni = 0; ni < 4; ni++)
            #pragma unroll
            for (int r = 0; r < 4; r++) { acc0[mi][ni][r] = 0.f; accS[mi][ni][r] = 0.f; }

    issue(0); issue(1);

    for (int c = 0; c < C; c++) {
        CP_WAIT1();
        __syncthreads();
        if (c + 2 < C) issue(c + 2);
        else CP_COMMIT();

        const uint32_t stb = sb + (c % 3) * STG1;
        #pragma unroll
        for (int ks = 0; ks < 4; ks++) {
            const int ch = 2 * ks + lch;
            uint32_t a0[2][4], a1[2][4];
            #pragma unroll
            for (int mi = 0; mi < 2; mi++) {
                const int row = wm * 32 + mi * 16 + lrow;
                ldm_x4(a0[mi][0], a0[mi][1], a0[mi][2], a0[mi][3], stb + sw(row, ch));
                ldm_x4(a1[mi][0], a1[mi][1], a1[mi][2], a1[mi][3], stb + TSZ + sw(row, ch));
            }
            uint32_t b0[4][2], b1[4][2];
            #pragma unroll
            for (int nj = 0; nj < 2; nj++) {
                const int row = wn * 32 + nj * 16 + lrow;
                uint32_t r0, r1, r2, r3;
                ldm_x4(r0, r1, r2, r3, stb + 2 * TSZ + sw(row, ch));
                b0[nj * 2 + 0][0] = r0; b0[nj * 2 + 0][1] = r2;
                b0[nj * 2 + 1][0] = r1; b0[nj * 2 + 1][1] = r3;
                ldm_x4(r0, r1, r2, r3, stb + 3 * TSZ + sw(row, ch));
                b1[nj * 2 + 0][0] = r0; b1[nj * 2 + 0][1] = r2;
                b1[nj * 2 + 1][0] = r1; b1[nj * 2 + 1][1] = r3;
            }
            #pragma unroll
            for (int mi = 0; mi < 2; mi++)
                #pragma unroll
                for (int ni = 0; ni < 4; ni++) {
                    hmma16816(acc0[mi][ni], a0[mi], b0[ni][0], b0[ni][1]);
                    hmma16816(accS[mi][ni], a0[mi], b1[ni][0], b1[ni][1]);
                    hmma16816(accS[mi][ni], a1[mi], b0[ni][0], b0[ni][1]);
                }
        }
    }

    const int erow = lane >> 2;
    const int ecol = (lane & 3) * 2;
    #pragma unroll
    for (int mi = 0; mi < 2; mi++) {
        #pragma unroll
        for (int r2i = 0; r2i < 2; r2i++) {
            const int m = m0 + wm * 32 + mi * 16 + erow + r2i * 8;
            const size_t rowo = (size_t)m * NH0;
            #pragma unroll
            for (int ni = 0; ni < 4; ni++) {
                #pragma unroll
                for (int cc = 0; cc < 2; cc++) {
                    const int n = n0 + wn * 32 + ni * 8 + ecol + cc;
                    if (n >= NH0) continue;
                    const size_t idx = rowo + n;
                    const float inp = acc0[mi][ni][r2i * 2 + cc]
                                    + SC1 * accS[mi][ni][r2i * 2 + cc]
                                    + fc_b[n];
                    const float tm = sigm(tau_m1[n]), ta = sigm(tau_adp1[n]);
                    const float sp = spk1[idx];
                    const float bb = ta * b1[idx] + (1.f - ta) * sp;
                    const float thre = BASE_THRE + BETA * bb;
                    const float mem = mem1[idx] * tm + (1.f - tm) * R_M * inp - thre * sp;
                    out_mem1[idx] = mem;
                    out_spk1[idx] = (mem - thre) > 0.f ? 1.f : 0.f;
                    out_b1[idx]   = bb;
                }
            }
        }
    }
}

// ---------------------------------------------------------------------------
// GEMM2: HMMA 2-term weight split. CTA 128x128, 512 thr, BK=64, 4 stages,
// XOR swizzle. Stage: A,W0,W1 each 16KB = 48KB; 4 stages = 192KB.
// grid: (32 m, 16 n, 2 modes)
// ---------------------------------------------------------------------------
#define STG2    (3 * TSZ)
#define SMEM_G2 (4 * STG2)

__global__ void __launch_bounds__(512, 1) gemm2_h2_kernel(
    const float* __restrict__ spk2, const float* __restrict__ mem2,
    const float* __restrict__ b2,
    float* __restrict__ out_mem2, float* __restrict__ out_spk2, float* __restrict__ out_b2)
{
    extern __shared__ char smem[];
    const uint32_t sb = smem_u32(smem);
    const int tid  = threadIdx.x;
    const int wid  = tid >> 5;
    const int lane = tid & 31;
    const int mode = blockIdx.z;
    const int m0   = blockIdx.x * 128;
    const int n0   = blockIdx.y * 128;

    const int Kpad = mode ? KP1 : KP0;
    const int C    = Kpad / 64;
    const __half* A0 = g_Ah + (size_t)m0 * KP1;
    const __half* W0 = (mode ? &g_Wi[0][0] : &g_Wo[0][0]) + (size_t)n0 * Kpad;
    const __half* W1 = (mode ? &g_Wi[1][0] : &g_Wo[1][0]) + (size_t)n0 * Kpad;

    // loader: 3072 cp16 per chunk, 6 per thread
    auto issue = [&](int c) {
        const uint32_t dst = sb + (c & 3) * STG2;
        const size_t ko = (size_t)c * 64;
        #pragma unroll
        for (int j = 0; j < 6; j++) {
            const int i = tid + j * 512;
            const int row = i >> 3, ch = i & 7;     // row 0..383
            const int q = row >> 7, r = row & 127;
            const __half* s = (q == 0) ? A0 : (q == 1 ? W0 : W1);
            const size_t stride = (q == 0) ? KP1 : Kpad;
            cp16(dst + q * TSZ + sw(r, ch), s + (size_t)r * stride + ko + ch * 8);
        }
        CP_COMMIT();
    };

    const int wm = wid >> 2;
    const int wn = wid & 3;
    const int lrow = lane & 15;
    const int lch  = lane >> 4;

    float acc0[2][4][4], acc1[2][4][4];
    #pragma unroll
    for (int mi = 0; mi < 2; mi++)
        #pragma unroll
        for (int ni = 0; ni < 4; ni++)
            #pragma unroll
            for (int r = 0; r < 4; r++) { acc0[mi][ni][r] = 0.f; acc1[mi][ni][r] = 0.f; }

    issue(0); issue(1); issue(2);

    for (int c = 0; c < C; c++) {
        CP_WAIT2();
        __syncthreads();
        if (c + 3 < C) issue(c + 3);
        else CP_COMMIT();

        const uint32_t stb = sb + (c & 3) * STG2;
        #pragma unroll
        for (int ks = 0; ks < 4; ks++) {
            const int ch = 2 * ks + lch;
            uint32_t a[2][4];
            #pragma unroll
            for (int mi = 0; mi < 2; mi++) {
                const int row = wm * 32 + mi * 16 + lrow;
                ldm_x4(a[mi][0], a[mi][1], a[mi][2], a[mi][3], stb + sw(row, ch));
            }
            #pragma unroll
            for (int t = 0; t < 2; t++) {
                uint32_t b[4][2];
                #pragma unroll
                for (int nj = 0; nj < 2; nj++) {
                    const int row = wn * 32 + nj * 16 + lrow;
                    uint32_t r0, r1, r2, r3;
                    ldm_x4(r0, r1, r2, r3, stb + (1 + t) * TSZ + sw(row, ch));
                    b[nj * 2 + 0][0] = r0; b[nj * 2 + 0][1] = r2;
                    b[nj * 2 + 1][0] = r1; b[nj * 2 + 1][1] = r3;
                }
                float (*acc)[4][4] = t ? acc1 : acc0;
                #pragma unroll
                for (int mi = 0; mi < 2; mi++)
                    #pragma unroll
                    for (int ni = 0; ni < 4; ni++)
                        hmma16816(acc[mi][ni], a[mi], b[ni][0], b[ni][1]);
            }
        }
    }

    const int erow = lane >> 2;
    const int ecol = (lane & 3) * 2;
    #pragma unroll
    for (int mi = 0; mi < 2; mi++) {
        #pragma unroll
        for (int r2i = 0; r2i < 2; r2i++) {
            const int m = m0 + wm * 32 + mi * 16 + erow + r2i * 8;
            const size_t rowo = (size_t)m * NH1;
            #pragma unroll
            for (int ni = 0; ni < 4; ni++) {
                #pragma unroll
                for (int cc = 0; cc < 2; cc++) {
                    const int nl = n0 + wn * 32 + ni * 8 + ecol + cc;
                    if (nl >= NR) continue;
                    const int g = mode * NR + nl;
                    const size_t idx = rowo + g;
                    const float v = acc0[mi][ni][r2i * 2 + cc]
                                  + SC1 * acc1[mi][ni][r2i * 2 + cc]
                                  + g_bias2[g];
                    const float tm = g_stm2[g], ta = g_sta2[g];
                    const float sp = spk2[idx];
                    const float bb = ta * b2[idx] + (1.f - ta) * sp;
                    const float thre = BASE_THRE + BETA * bb;
                    const float mem = mem2[idx] * tm + (1.f - tm) * R_M * v - thre * sp;
                    out_mem2[idx] = mem;
                    out_spk2[idx] = (mem - thre) > 0.f ? 1.f : 0.f;
                    out_b2[idx]   = bb;
                }
            }
        }
    }
}

// ---------------------------------------------------------------------------
// Head: pooling + mem_out update + log_softmax
// ---------------------------------------------------------------------------
__global__ void head_kernel(
    const float* __restrict__ spk2n, const float* __restrict__ mem_out,
    const float* __restrict__ out_tau_m,
    float* __restrict__ log_sm, float* __restrict__ mem_out_n)
{
    __shared__ float xo[NOUT];
    const int row = blockIdx.x;
    const int w = threadIdx.x >> 5, lane = threadIdx.x & 31;
    float s = 0.f;
    const float* p = spk2n + (size_t)row * NH1 + w * 200;
    for (int i = lane; i < 200; i += 32) s += p[i];
    #pragma unroll
    for (int o = 16; o > 0; o >>= 1) s += __shfl_down_sync(0xffffffffu, s, o);
    if (lane == 0) xo[w] = s;
    __syncthreads();
    if (threadIdx.x == 0) {
        float v[NOUT];
        float mx = -1e30f;
        #pragma unroll
        for (int o = 0; o < NOUT; o++) {
            const float m = mem_out[(size_t)row * NOUT + o];
            const float mo = m + (xo[o] - m) * sigm(out_tau_m[o]);
            v[o] = mo; mem_out_n[(size_t)row * NOUT + o] = mo;
            mx = fmaxf(mx, mo);
        }
        float se = 0.f;
        #pragma unroll
        for (int o = 0; o < NOUT; o++) se += expf(v[o] - mx);
        const float lse = mx + logf(se);
        #pragma unroll
        for (int o = 0; o < NOUT; o++) log_sm[(size_t)row * NOUT + o] = v[o] - lse;
    }
}

// ---------------------------------------------------------------------------
// Launch
// ---------------------------------------------------------------------------
extern "C" void kernel_launch(void* const* d_in, const int* in_sizes, int n_in,
                              void* d_out, int out_size)
{
    const float* x_t       = (const float*)d_in[0];
    const float* mem1      = (const float*)d_in[1];
    const float* spk1      = (const float*)d_in[2];
    const float* b1        = (const float*)d_in[3];
    const float* mem2      = (const float*)d_in[4];
    const float* spk2      = (const float*)d_in[5];
    const float* b2        = (const float*)d_in[6];
    const float* mem_out   = (const float*)d_in[7];
    const float* fc_w      = (const float*)d_in[8];
    const float* fc_b      = (const float*)d_in[9];
    const float* tau_adp1  = (const float*)d_in[10];
    const float* tau_m1    = (const float*)d_in[11];
    const float* x2in_w    = (const float*)d_in[12];
    const float* x2in_b    = (const float*)d_in[13];
    const float* rec4in_w  = (const float*)d_in[14];
    const float* rec4in_b  = (const float*)d_in[15];
    const float* in2out_w  = (const float*)d_in[16];
    const float* in2out_b  = (const float*)d_in[17];
    const float* rec4out_w = (const float*)d_in[18];
    const float* rec4out_b = (const float*)d_in[19];
    const float* out2in_w  = (const float*)d_in[20];
    const float* out2in_b  = (const float*)d_in[21];
    const float* tau_adp2  = (const float*)d_in[22];
    const float* tau_m2    = (const float*)d_in[23];
    const float* out_tau_m = (const float*)d_in[24];

    float* out = (float*)d_out;
    const size_t BH = (size_t)NB * NH0;
    float* log_sm    = out;
    float* mem1n     = out + (size_t)NB * NOUT;
    float* spk1n     = mem1n + BH;
    float* b1n       = spk1n + BH;
    float* mem2n     = b1n + BH;
    float* spk2n     = mem2n + BH;
    float* b2n       = spk2n + BH;
    float* mem_out_n = b2n + BH;

    cudaFuncSetAttribute(gemm1_h2_kernel, cudaFuncAttributeMaxDynamicSharedMemorySize,
                         SMEM_G1);
    cudaFuncSetAttribute(gemm2_h2_kernel, cudaFuncAttributeMaxDynamicSharedMemorySize,
                         SMEM_G2);

    {
        const long T = 4L * NR * NR + (long)NR * NH0 + (long)NH0 * IN_D
                     + (long)NB * IN_D + NH1;
        convPre_kernel<<<(int)((T + 255) / 256), 256>>>(
            rec4out_w, in2out_w, out2in_w, rec4in_w, x2in_w, fc_w, x_t,
            tau_m2, tau_adp2, rec4out_b, in2out_b, out2in_b, rec4in_b, x2in_b);
    }

    gemm1_h2_kernel<<<dim3(32, 32), 512, SMEM_G1>>>(
        fc_b, mem1, spk1, b1, tau_m1, tau_adp1, mem1n, spk1n, b1n);

    {
        const long T = 2L * NB * NH1;
        convA_kernel<<<(int)((T + 255) / 256), 256>>>(spk2, spk1n);
    }

    gemm2_h2_kernel<<<dim3(32, 16, 2), 512, SMEM_G2>>>(
        spk2, mem2, b2, mem2n, spk2n, b2n);

    head_kernel<<<NB, 320>>>(spk2n, mem_out, out_tau_m, log_sm, mem_out_n);
}